// round 13
// baseline (speedup 1.0000x reference)
#include <cuda_runtime.h>
#include <cuda_bf16.h>
#include <cstdint>

#define DIM   1024
#define NQ    512
#define NKV   2048
#define NCTX  2560
#define BATCH 4
#define HEADS 16
#define DH    64

// ---------------- scratch (no allocs allowed) ----------------
__device__ __nv_bfloat16 g_kvn[(long)BATCH * NCTX * DIM];  // LN outputs (bf16)
__device__ __nv_bfloat16 g_wt [4L * DIM * DIM];            // transposed bf16 weights [n][k]
__device__ __nv_bfloat16 g_q  [(long)BATCH * NQ   * DIM];
__device__ __nv_bfloat16 g_k  [(long)BATCH * NCTX * DIM];
__device__ __nv_bfloat16 g_v  [(long)BATCH * NCTX * DIM];
__device__ __nv_bfloat16 g_att[(long)BATCH * NQ   * DIM];  // attention output (bf16)

// ================= PTX helpers (base sm_103 features only) =================
__device__ __forceinline__ uint32_t smem_u32(const void* p) {
    uint32_t a;
    asm("{ .reg .u64 t; cvta.to.shared.u64 t, %1; cvt.u32.u64 %0, t; }" : "=r"(a) : "l"(p));
    return a;
}
__device__ __forceinline__ void cp16(uint32_t dst, const void* src) {
    asm volatile("cp.async.cg.shared.global [%0], [%1], 16;" :: "r"(dst), "l"(src));
}
__device__ __forceinline__ void cp_commit() {
    asm volatile("cp.async.commit_group;" ::: "memory");
}
template <int N>
__device__ __forceinline__ void cp_wait() {
    asm volatile("cp.async.wait_group %0;" :: "n"(N) : "memory");
}
#define LDSM_X4(r0, r1, r2, r3, addr) \
    asm volatile("ldmatrix.sync.aligned.m8n8.x4.shared.b16 {%0,%1,%2,%3}, [%4];" \
        : "=r"(r0), "=r"(r1), "=r"(r2), "=r"(r3) : "r"(addr))
#define LDSM_X4_T(r0, r1, r2, r3, addr) \
    asm volatile("ldmatrix.sync.aligned.m8n8.x4.trans.shared.b16 {%0,%1,%2,%3}, [%4];" \
        : "=r"(r0), "=r"(r1), "=r"(r2), "=r"(r3) : "r"(addr))
#define MMA16816(d, a0, a1, a2, a3, b0, b1) \
    asm volatile("mma.sync.aligned.m16n8k16.row.col.f32.bf16.bf16.f32 " \
        "{%0,%1,%2,%3}, {%4,%5,%6,%7}, {%8,%9}, {%0,%1,%2,%3};" \
        : "+f"((d)[0]), "+f"((d)[1]), "+f"((d)[2]), "+f"((d)[3]) \
        : "r"(a0), "r"(a1), "r"(a2), "r"(a3), "r"(b0), "r"(b1))

__device__ __forceinline__ uint32_t pack_bf16(float x, float y) {
    __nv_bfloat162 p = __floats2bfloat162_rn(x, y);
    return *reinterpret_cast<uint32_t*>(&p);
}

// scale * log2(e), folded into Q at projection time
#define QSCALE 0.1803368801111204f

// ---------------- merged LayerNorm (fp32 in, bf16 out) ----------------
__global__ __launch_bounds__(256)
void ln_kernel(const float* __restrict__ kv, const float* __restrict__ query,
               __nv_bfloat16* __restrict__ y,
               const float* __restrict__ g_kv, const float* __restrict__ b_kv,
               const float* __restrict__ g_q,  const float* __restrict__ b_q)
{
    __shared__ float red[8];
    __shared__ float s_mu, s_rstd;
    int row = blockIdx.x;
    int b = row / NCTX;
    int r = row - b * NCTX;
    const float* xr;
    const float *gg_p, *bb_p;
    if (r < NKV) { xr = kv    + ((long)b * NKV + r)        * DIM; gg_p = g_kv; bb_p = b_kv; }
    else         { xr = query + ((long)b * NQ + (r - NKV)) * DIM; gg_p = g_q;  bb_p = b_q;  }
    __nv_bfloat16* yr = y + (long)row * DIM;
    int tid = threadIdx.x;

    float4 v = *(const float4*)(xr + tid * 4);
    float s = v.x + v.y + v.z + v.w;
    #pragma unroll
    for (int o = 16; o > 0; o >>= 1) s += __shfl_xor_sync(0xffffffffu, s, o);
    if ((tid & 31) == 0) red[tid >> 5] = s;
    __syncthreads();
    if (tid == 0) {
        float t = 0.f;
        #pragma unroll
        for (int i = 0; i < 8; i++) t += red[i];
        s_mu = t * (1.f / DIM);
    }
    __syncthreads();
    float mu = s_mu;
    float d0 = v.x - mu, d1 = v.y - mu, d2 = v.z - mu, d3 = v.w - mu;
    float q = d0*d0 + d1*d1 + d2*d2 + d3*d3;
    #pragma unroll
    for (int o = 16; o > 0; o >>= 1) q += __shfl_xor_sync(0xffffffffu, q, o);
    if ((tid & 31) == 0) red[tid >> 5] = q;
    __syncthreads();
    if (tid == 0) {
        float t = 0.f;
        #pragma unroll
        for (int i = 0; i < 8; i++) t += red[i];
        s_rstd = rsqrtf(t * (1.f / DIM) + 1e-5f);
    }
    __syncthreads();
    float rstd = s_rstd;
    float4 gg = *(const float4*)(gg_p + tid * 4);
    float4 b4 = *(const float4*)(bb_p + tid * 4);
    float o0 = d0 * rstd * gg.x + b4.x;
    float o1 = d1 * rstd * gg.y + b4.y;
    float o2 = d2 * rstd * gg.z + b4.z;
    float o3 = d3 * rstd * gg.w + b4.w;
    uint2 u;
    u.x = pack_bf16(o0, o1);
    u.y = pack_bf16(o2, o3);
    *reinterpret_cast<uint2*>(yr + tid * 4) = u;
}

// ---------------- weight transpose+convert (all 4 in one launch) ----------------
__global__ __launch_bounds__(256)
void wtrans_kernel(const float* __restrict__ W0, const float* __restrict__ W1,
                   const float* __restrict__ W2, const float* __restrict__ W3,
                   __nv_bfloat16* __restrict__ Wt)
{
    __shared__ float s[32][33];
    const float* W = (blockIdx.z == 0) ? W0 : (blockIdx.z == 1) ? W1
                   : (blockIdx.z == 2) ? W2 : W3;
    __nv_bfloat16* Wo = Wt + (long)blockIdx.z * DIM * DIM;
    int tx = threadIdx.x, ty = threadIdx.y;
    int n0 = blockIdx.x * 32, k0 = blockIdx.y * 32;
    #pragma unroll
    for (int i = 0; i < 32; i += 8)
        s[ty + i][tx] = W[(long)(k0 + ty + i) * DIM + n0 + tx];
    __syncthreads();
    #pragma unroll
    for (int i = 0; i < 32; i += 8)
        Wo[(long)(n0 + ty + i) * DIM + k0 + tx] = __float2bfloat16(s[tx][ty + i]);
}

#define GK   1024
#define NIT  16               // K / 64

// ================= O-GEMM machinery (R10-proven): 128x128, warp 64x32 =================
#define ST        3
#define STAGE_B   32768
#define GEMM_SMEM (ST * STAGE_B + 1024)

struct GemmCtx {
    uint32_t base;
    const __nv_bfloat16 *Ab, *Bb;
    int tid, lane, wm, wn;
};

__device__ __forceinline__ void gemm_load_stage(const GemmCtx& g, int it) {
    uint32_t sA = g.base + (it % ST) * STAGE_B;
    uint32_t sB = sA + 16384;
    int row = g.tid >> 1;
    int cb  = (g.tid & 1) * 4;
    const __nv_bfloat16* ga = g.Ab + (long)row * GK + it * 64 + cb * 8;
    const __nv_bfloat16* gb = g.Bb + (long)row * GK + it * 64 + cb * 8;
    uint32_t ro = row * 128;
    #pragma unroll
    for (int c = 0; c < 4; c++) {
        uint32_t sw = (((cb + c) ^ (row & 7)) << 4);
        cp16(sA + ro + sw, ga + c * 8);
        cp16(sB + ro + sw, gb + c * 8);
    }
    cp_commit();
}

__device__ __forceinline__ void gemm_mainloop(const GemmCtx& g, float acc[4][4][4]) {
    const int a_r8 = (g.lane & 7) + ((g.lane >> 3) & 1) * 8;
    const int a_cq = (g.lane >> 4);
    const int b_r8 = (g.lane & 7) + ((g.lane >> 4) & 1) * 8;
    const int b_cq = (g.lane >> 3) & 1;

    gemm_load_stage(g, 0);
    gemm_load_stage(g, 1);

    for (int it = 0; it < NIT; it++) {
        cp_wait<1>();
        __syncthreads();
        if (it + 2 < NIT) gemm_load_stage(g, it + 2);
        else cp_commit();

        uint32_t sA = g.base + (it % ST) * STAGE_B;
        uint32_t sB = sA + 16384;

        #pragma unroll
        for (int ks = 0; ks < 4; ks++) {
            uint32_t a[4][4];
            #pragma unroll
            for (int i = 0; i < 4; i++) {
                int r = g.wm * 64 + i * 16 + a_r8;
                int c = ks * 2 + a_cq;
                LDSM_X4(a[i][0], a[i][1], a[i][2], a[i][3],
                        sA + r * 128 + ((c ^ (r & 7)) << 4));
            }
            uint32_t b[2][4];
            #pragma unroll
            for (int jj = 0; jj < 2; jj++) {
                int r = g.wn * 32 + jj * 16 + b_r8;
                int c = ks * 2 + b_cq;
                LDSM_X4(b[jj][0], b[jj][1], b[jj][2], b[jj][3],
                        sB + r * 128 + ((c ^ (r & 7)) << 4));
            }
            #pragma unroll
            for (int i = 0; i < 4; i++)
                #pragma unroll
                for (int j = 0; j < 4; j++)
                    MMA16816(acc[i][j], a[i][0], a[i][1], a[i][2], a[i][3],
                             b[j >> 1][(j & 1) * 2], b[j >> 1][(j & 1) * 2 + 1]);
        }
    }
}

// ================= qkv GEMM machinery: 256x128 CTA tile, warp 64x64 =================
// 8 warps (4M x 2N), BK=64, ST=3. Per k16/warp: 8 LDSM.x4 -> 32 MMAs (4:1).
#define STAGE_B2   49152           // A 32KB (256 rows) + B 16KB (128 rows)
#define GEMM2_SMEM (ST * STAGE_B2 + 1024)

__global__ __launch_bounds__(256, 1)
void gemm_qkv_kernel(const __nv_bfloat16* __restrict__ A,
                     const __nv_bfloat16* __restrict__ wt,
                     const float* __restrict__ bq, const float* __restrict__ bk,
                     const float* __restrict__ bv,
                     __nv_bfloat16* __restrict__ qb, __nv_bfloat16* __restrict__ kb,
                     __nv_bfloat16* __restrict__ vb)
{
    // grid (24, 40): x<8 -> K cols x*128; 8<=x<16 -> V cols (x-8)*128;
    // 16<=x<24 -> Q cols (x-16)*128, only on q-row blocks (y%10 >= 8).
    const int x = blockIdx.x, y = blockIdx.y;
    const float* bias;
    __nv_bfloat16* Out;
    const __nv_bfloat16* Bt;
    long orow;
    int col0;
    float osc = 1.f;
    if (x < 16) {
        Bt   = wt + 1L * DIM * DIM + (long)x * 128 * GK;  // [Wk;Wv] contiguous
        bias = (x < 8) ? bk : bv;
        Out  = (x < 8) ? kb : vb;
        col0 = (x & 7) * 128;
        orow = (long)y * 256;
    } else {
        int ym = y % 10;
        if (ym < 8) return;                     // not a q-row block
        Bt   = wt + (long)(x - 16) * 128 * GK;  // Wq
        bias = bq;
        Out  = qb;
        col0 = (x - 16) * 128;
        orow = (long)(y / 10) * NQ + (long)(ym - 8) * 256;
        osc  = QSCALE;
    }

    extern __shared__ char smraw[];
    uint32_t base = (smem_u32(smraw) + 1023u) & ~1023u;
    const int tid  = threadIdx.x;
    const int lane = tid & 31;
    const int wid  = tid >> 5;
    const int wm   = wid & 3;       // 0..3 (M, 64 rows each)
    const int wn   = wid >> 2;      // 0..1 (N, 64 cols each)

    const __nv_bfloat16* Ab = A + (long)y * 256 * GK;
    const __nv_bfloat16* Bb = Bt;

    // loads: A 256 rows x 8 chunks (1 row/thread); B 128 rows x 8 chunks (2 thr/row x 4)
    const int b_lr = tid >> 1;
    const int b_cb = (tid & 1) * 4;
    auto load_stage = [&](int it) {
        uint32_t sA = base + (it % ST) * STAGE_B2;
        uint32_t sB = sA + 32768;
        const __nv_bfloat16* ga = Ab + (long)tid * GK + it * 64;
        #pragma unroll
        for (int c = 0; c < 8; c++)
            cp16(sA + tid * 128 + ((c ^ (tid & 7)) << 4), ga + c * 8);
        const __nv_bfloat16* gb = Bb + (long)b_lr * GK + it * 64 + b_cb * 8;
        #pragma unroll
        for (int c = 0; c < 4; c++)
            cp16(sB + b_lr * 128 + (((b_cb + c) ^ (b_lr & 7)) << 4), gb + c * 8);
        cp_commit();
    };

    float acc[4][8][4];
    #pragma unroll
    for (int i = 0; i < 4; i++)
        #pragma unroll
        for (int j = 0; j < 8; j++)
            #pragma unroll
            for (int q = 0; q < 4; q++) acc[i][j][q] = 0.f;

    load_stage(0);
    load_stage(1);

    const int a_r8 = (lane & 7) + ((lane >> 3) & 1) * 8;
    const int a_cq = (lane >> 4);
    const int b_r8 = (lane & 7) + ((lane >> 4) & 1) * 8;
    const int b_cq = (lane >> 3) & 1;

    for (int it = 0; it < NIT; it++) {
        cp_wait<1>();
        __syncthreads();
        if (it + 2 < NIT) load_stage(it + 2);
        else cp_commit();

        uint32_t sA = base + (it % ST) * STAGE_B2;
        uint32_t sB = sA + 32768;

        #pragma unroll
        for (int ks = 0; ks < 4; ks++) {
            uint32_t a[4][4];
            #pragma unroll
            for (int i = 0; i < 4; i++) {
                int r = wm * 64 + i * 16 + a_r8;
                int c = ks * 2 + a_cq;
                LDSM_X4(a[i][0], a[i][1], a[i][2], a[i][3],
                        sA + r * 128 + ((c ^ (r & 7)) << 4));
            }
            uint32_t b[4][4];
            #pragma unroll
            for (int jj = 0; jj < 4; jj++) {
                int r = wn * 64 + jj * 16 + b_r8;
                int c = ks * 2 + b_cq;
                LDSM_X4(b[jj][0], b[jj][1], b[jj][2], b[jj][3],
                        sB + r * 128 + ((c ^ (r & 7)) << 4));
            }
            #pragma unroll
            for (int i = 0; i < 4; i++)
                #pragma unroll
                for (int j = 0; j < 8; j++)
                    MMA16816(acc[i][j], a[i][0], a[i][1], a[i][2], a[i][3],
                             b[j >> 1][(j & 1) * 2], b[j >> 1][(j & 1) * 2 + 1]);
        }
    }

    const long rowbase = (orow + wm * 64) * (long)DIM;
    const int  cw = col0 + wn * 64;
    #pragma unroll
    for (int i = 0; i < 4; i++) {
        int rr = i * 16 + (lane >> 2);
        #pragma unroll
        for (int j = 0; j < 8; j++) {
            int cc = cw + j * 8 + (lane & 3) * 2;
            float bx = bias[cc], by = bias[cc + 1];
            long off0 = rowbase + (long)rr * DIM + cc;
            long off1 = off0 + 8L * DIM;
            *(uint32_t*)(Out + off0) = pack_bf16((acc[i][j][0] + bx) * osc,
                                                 (acc[i][j][1] + by) * osc);
            *(uint32_t*)(Out + off1) = pack_bf16((acc[i][j][2] + bx) * osc,
                                                 (acc[i][j][3] + by) * osc);
        }
    }
}

// ---------------- O projection GEMM (f32 out + bias + resid, 256 threads, R10) ------
__global__ __launch_bounds__(256)
void gemm_o_kernel(const __nv_bfloat16* __restrict__ A,
                   const __nv_bfloat16* __restrict__ Bt,
                   const float* __restrict__ bias,
                   const float* __restrict__ resid,
                   float* __restrict__ C)
{
    extern __shared__ char smraw[];
    GemmCtx g;
    g.base = (smem_u32(smraw) + 1023u) & ~1023u;
    g.tid  = threadIdx.x;
    g.lane = g.tid & 31;
    int wid = g.tid >> 5;
    g.wm = wid & 1;
    g.wn = wid >> 1;
    g.Ab = A + (long)blockIdx.y * 128 * GK;
    g.Bb = Bt + (long)blockIdx.x * 128 * GK;

    float acc[4][4][4];
    #pragma unroll
    for (int i = 0; i < 4; i++)
        #pragma unroll
        for (int j = 0; j < 4; j++)
            #pragma unroll
            for (int q = 0; q < 4; q++) acc[i][j][q] = 0.f;

    gemm_mainloop(g, acc);

    const long rowbase = ((long)blockIdx.y * 128 + g.wm * 64) * (long)DIM;
    const int  col0    = blockIdx.x * 128 + g.wn * 32;
    #pragma unroll
    for (int i = 0; i < 4; i++) {
        int rr = i * 16 + (g.lane >> 2);
        #pragma unroll
        for (int j = 0; j < 4; j++) {
            int cc = col0 + j * 8 + (g.lane & 3) * 2;
            float bx = bias[cc], by = bias[cc + 1];
            long off0 = rowbase + (long)rr * DIM + cc;
            long off1 = off0 + 8L * DIM;
            float2 r0 = *(const float2*)(resid + off0);
            float2 r1 = *(const float2*)(resid + off1);
            float2 o0, o1;
            o0.x = acc[i][j][0] + bx + r0.x; o0.y = acc[i][j][1] + by + r0.y;
            o1.x = acc[i][j][2] + bx + r1.x; o1.y = acc[i][j][3] + by + r1.y;
            *(float2*)(C + off0) = o0;
            *(float2*)(C + off1) = o1;
        }
    }
}

// ---------------- Tensor-core flash attention (R12, fixed-offset softmax) ----------
// 256 q-rows per CTA (8 warps x 32 rows, two 16-row halves), 64-key tiles,
// 4-stage cp.async ring, one barrier per tile, K/V fragments reused (4:1).
#define NT_KV      (NCTX / 64)            // 40
#define KVST       4
#define ATTN_SMEM  (32768 + KVST * 16384) // Q 32KB + 4 stages (K 8KB + V 8KB)

__global__ __launch_bounds__(256, 1)
void fattn_kernel(const __nv_bfloat16* __restrict__ Q,
                  const __nv_bfloat16* __restrict__ K,
                  const __nv_bfloat16* __restrict__ V,
                  __nv_bfloat16* __restrict__ O)
{
    extern __shared__ char smraw[];
    uint32_t base = (smem_u32(smraw) + 127u) & ~127u;
    uint32_t sQ  = base;
    uint32_t sKV = base + 32768;

    const int tid  = threadIdx.x;
    const int lane = tid & 31;
    const int wq   = tid >> 5;
    const int qt = blockIdx.x, h = blockIdx.y, b = blockIdx.z;

    const __nv_bfloat16* Qg = Q + ((long)(b * NQ + qt * 256)) * DIM + h * DH;
    const __nv_bfloat16* Kg = K + (long)b * NCTX * DIM + h * DH;
    const __nv_bfloat16* Vg = V + (long)b * NCTX * DIM + h * DH;

    {
        int lr = tid;
        const __nv_bfloat16* src = Qg + (long)lr * DIM;
        #pragma unroll
        for (int c = 0; c < 8; c++)
            cp16(sQ + lr * 128 + ((c ^ (lr & 7)) << 4), src + c * 8);
    }
    const int kvr = tid >> 2;
    const int kvc = (tid & 3) * 2;
    auto load_kv = [&](int t) {
        uint32_t sK = sKV + (t % KVST) * 16384;
        const __nv_bfloat16* ks = Kg + (long)(t * 64 + kvr) * DIM + kvc * 8;
        const __nv_bfloat16* vs = Vg + (long)(t * 64 + kvr) * DIM + kvc * 8;
        #pragma unroll
        for (int c = 0; c < 2; c++) {
            uint32_t sw = ((kvc + c) ^ (kvr & 7)) << 4;
            cp16(sK + kvr * 128 + sw, ks + c * 8);
            cp16(sK + 8192 + kvr * 128 + sw, vs + c * 8);
        }
    };
    load_kv(0);
    cp_commit();
    load_kv(1);
    cp_commit();
    load_kv(2);
    cp_commit();
    cp_wait<2>();
    __syncthreads();

    uint32_t aq0[4][4], aq1[4][4];
    {
        int rb = (lane & 7) + ((lane >> 3) & 1) * 8;
        int cc = lane >> 4;
        #pragma unroll
        for (int ks = 0; ks < 4; ks++) {
            int c = ks * 2 + cc;
            int r0 = wq * 32 + rb;
            int r1 = wq * 32 + 16 + rb;
            LDSM_X4(aq0[ks][0], aq0[ks][1], aq0[ks][2], aq0[ks][3],
                    sQ + r0 * 128 + ((c ^ (r0 & 7)) << 4));
            LDSM_X4(aq1[ks][0], aq1[ks][1], aq1[ks][2], aq1[ks][3],
                    sQ + r1 * 128 + ((c ^ (r1 & 7)) << 4));
        }
    }

    float l00 = 0.f, l01 = 0.f, l10 = 0.f, l11 = 0.f;
    float o0[8][4], o1[8][4];
    #pragma unroll
    for (int nt = 0; nt < 8; nt++)
        #pragma unroll
        for (int q = 0; q < 4; q++) { o0[nt][q] = 0.f; o1[nt][q] = 0.f; }

    const int r_ab = (lane & 7) + ((lane >> 3) & 1) * 8;
    const int r_b  = (lane & 7) + ((lane >> 4) & 1) * 8;
    const int cq_a = lane >> 4;
    const int cq_b = (lane >> 3) & 1;

    for (int t = 0; t < NT_KV; t++) {
        if (t + 3 < NT_KV) load_kv(t + 3);
        cp_commit();

        uint32_t sK = sKV + (t % KVST) * 16384;
        uint32_t sV = sK + 8192;

        float st0[8][4], st1[8][4];
        #pragma unroll
        for (int nt = 0; nt < 8; nt++)
            #pragma unroll
            for (int q = 0; q < 4; q++) { st0[nt][q] = 0.f; st1[nt][q] = 0.f; }

        #pragma unroll
        for (int ks = 0; ks < 4; ks++) {
            #pragma unroll
            for (int kg = 0; kg < 4; kg++) {
                int r = kg * 16 + r_b;
                int c = ks * 2 + cq_b;
                uint32_t b0, b1, b2, b3;
                LDSM_X4(b0, b1, b2, b3, sK + r * 128 + ((c ^ (r & 7)) << 4));
                MMA16816(st0[2 * kg],     aq0[ks][0], aq0[ks][1], aq0[ks][2], aq0[ks][3], b0, b1);
                MMA16816(st0[2 * kg + 1], aq0[ks][0], aq0[ks][1], aq0[ks][2], aq0[ks][3], b2, b3);
                MMA16816(st1[2 * kg],     aq1[ks][0], aq1[ks][1], aq1[ks][2], aq1[ks][3], b0, b1);
                MMA16816(st1[2 * kg + 1], aq1[ks][0], aq1[ks][1], aq1[ks][2], aq1[ks][3], b2, b3);
            }
        }

        uint32_t pa0[4][4], pa1[4][4];
        #pragma unroll
        for (int nt = 0; nt < 8; nt++) {
            float a0 = exp2f(st0[nt][0]);
            float a1 = exp2f(st0[nt][1]);
            float a2 = exp2f(st0[nt][2]);
            float a3 = exp2f(st0[nt][3]);
            l00 += a0 + a1;
            l01 += a2 + a3;
            pa0[nt >> 1][(nt & 1) * 2 + 0] = pack_bf16(a0, a1);
            pa0[nt >> 1][(nt & 1) * 2 + 1] = pack_bf16(a2, a3);
            float c0 = exp2f(st1[nt][0]);
            float c1 = exp2f(st1[nt][1]);
            float c2 = exp2f(st1[nt][2]);
            float c3 = exp2f(st1[nt][3]);
            l10 += c0 + c1;
            l11 += c2 + c3;
            pa1[nt >> 1][(nt & 1) * 2 + 0] = pack_bf16(c0, c1);
            pa1[nt >> 1][(nt & 1) * 2 + 1] = pack_bf16(c2, c3);
        }

        #pragma unroll
        for (int kt = 0; kt < 4; kt++) {
            #pragma unroll
            for (int np = 0; np < 4; np++) {
                int r = kt * 16 + r_ab;
                int c = np * 2 + cq_a;
                uint32_t b0, b1, b2, b3;
                LDSM_X4_T(b0, b1, b2, b3, sV + r * 128 + ((c ^ (r & 7)) << 4));
                MMA16816(o0[2 * np],     pa0[kt][0], pa0[kt][1], pa0[kt][2], pa0[kt][3], b0, b1);
                MMA16816(o0[2 * np + 1], pa0[kt][0], pa0[kt][1], pa0[kt][2], pa0[kt][3], b2, b3);
                MMA16816(o1[2 * np],     pa1[kt][0], pa1[kt][1], pa1[kt][2], pa1[kt][3], b0, b1);
                MMA16816(o1[2 * np + 1], pa1[kt][0], pa1[kt][1], pa1[kt][2], pa1[kt][3], b2, b3);
            }
        }

        cp_wait<2>();
        __syncthreads();
    }

    l00 += __shfl_xor_sync(0xffffffffu, l00, 1);
    l00 += __shfl_xor_sync(0xffffffffu, l00, 2);
    l01 += __shfl_xor_sync(0xffffffffu, l01, 1);
    l01 += __shfl_xor_sync(0xffffffffu, l01, 2);
    l10 += __shfl_xor_sync(0xffffffffu, l10, 1);
    l10 += __shfl_xor_sync(0xffffffffu, l10, 2);
    l11 += __shfl_xor_sync(0xffffffffu, l11, 1);
    l11 += __shfl_xor_sync(0xffffffffu, l11, 2);

    float i00 = 1.f / l00, i01 = 1.f / l01, i10 = 1.f / l10, i11 = 1.f / l11;
    int row = qt * 256 + wq * 32 + (lane >> 2);
    __nv_bfloat16* Og = O + ((long)(b * NQ + row)) * DIM + h * DH + (lane & 3) * 2;
    #pragma unroll
    for (int nt = 0; nt < 8; nt++) {
        *(uint32_t*)(Og + nt * 8)             = pack_bf16(o0[nt][0] * i00, o0[nt][1] * i00);
        *(uint32_t*)(Og + 8L * DIM + nt * 8)  = pack_bf16(o0[nt][2] * i01, o0[nt][3] * i01);
        *(uint32_t*)(Og + 16L * DIM + nt * 8) = pack_bf16(o1[nt][0] * i10, o1[nt][1] * i10);
        *(uint32_t*)(Og + 24L * DIM + nt * 8) = pack_bf16(o1[nt][2] * i11, o1[nt][3] * i11);
    }
}

// ---------------- launch ----------------
extern "C" void kernel_launch(void* const* d_in, const int* in_sizes, int n_in,
                              void* d_out, int out_size)
{
    const float* query   = (const float*)d_in[0];
    const float* kv      = (const float*)d_in[1];
    const float* ln_q_g  = (const float*)d_in[2];
    const float* ln_q_b  = (const float*)d_in[3];
    const float* ln_kv_g = (const float*)d_in[4];
    const float* ln_kv_b = (const float*)d_in[5];
    const float* Wq = (const float*)d_in[6];
    const float* bq = (const float*)d_in[7];
    const float* Wk = (const float*)d_in[8];
    const float* bk = (const float*)d_in[9];
    const float* Wv = (const float*)d_in[10];
    const float* bv = (const float*)d_in[11];
    const float* Wo = (const float*)d_in[12];
    const float* bo = (const float*)d_in[13];
    float* out = (float*)d_out;

    __nv_bfloat16 *kvn, *wt, *qb, *kb, *vb, *ab;
    cudaGetSymbolAddress((void**)&kvn, g_kvn);
    cudaGetSymbolAddress((void**)&wt,  g_wt);
    cudaGetSymbolAddress((void**)&qb,  g_q);
    cudaGetSymbolAddress((void**)&kb,  g_k);
    cudaGetSymbolAddress((void**)&vb,  g_v);
    cudaGetSymbolAddress((void**)&ab,  g_att);

    cudaFuncSetAttribute((const void*)gemm_qkv_kernel,
                         cudaFuncAttributeMaxDynamicSharedMemorySize, GEMM2_SMEM);
    cudaFuncSetAttribute((const void*)gemm_o_kernel,
                         cudaFuncAttributeMaxDynamicSharedMemorySize, GEMM_SMEM);
    cudaFuncSetAttribute((const void*)fattn_kernel,
                         cudaFuncAttributeMaxDynamicSharedMemorySize, ATTN_SMEM);

    // transpose+convert weights to bf16 [N][K] (one launch for all four)
    {
        dim3 grid(DIM / 32, DIM / 32, 4), blk(32, 8);
        wtrans_kernel<<<grid, blk>>>(Wq, Wk, Wv, Wo, wt);
    }

    // merged LayerNorm -> bf16 kvn (kv rows then q rows per batch)
    ln_kernel<<<BATCH * NCTX, 256>>>(kv, query, kvn,
                                     ln_kv_g, ln_kv_b, ln_q_g, ln_q_b);

    // fused Q + K + V projections, 256x128 tiles (24 x-blocks; 40 y-blocks of 256 rows)
    {
        dim3 grid(24, BATCH * NCTX / 256, 1);
        gemm_qkv_kernel<<<grid, 256, GEMM2_SMEM>>>(kvn, wt, bq, bk, bv, qb, kb, vb);
    }

    // tensor-core flash attention (bf16 in/out), 256 q-rows per CTA
    {
        dim3 grid(NQ / 256, HEADS, BATCH);
        fattn_kernel<<<grid, 256, ATTN_SMEM>>>(qb, kb, vb, ab);
    }

    // out = attn @ Wo + bo + residual(query), 128x128 tiles
    {
        dim3 grid(DIM / 128, BATCH * NQ / 128, 1);
        gemm_o_kernel<<<grid, 256, GEMM_SMEM>>>(ab, wt + 3L * DIM * DIM, bo, query, out);
    }
}

// round 14
// speedup vs baseline: 1.1938x; 1.1938x over previous
#include <cuda_runtime.h>
#include <cuda_bf16.h>
#include <cstdint>

#define DIM   1024
#define NQ    512
#define NKV   2048
#define NCTX  2560
#define BATCH 4
#define HEADS 16
#define DH    64

// ---------------- scratch (no allocs allowed) ----------------
__device__ __nv_bfloat16 g_kvn[(long)BATCH * NCTX * DIM];  // LN outputs (bf16)
__device__ __nv_bfloat16 g_wt [4L * DIM * DIM];            // transposed bf16 weights [n][k]
__device__ __nv_bfloat16 g_q  [(long)BATCH * NQ   * DIM];
__device__ __nv_bfloat16 g_k  [(long)BATCH * NCTX * DIM];
__device__ __nv_bfloat16 g_v  [(long)BATCH * NCTX * DIM];
__device__ __nv_bfloat16 g_att[(long)BATCH * NQ   * DIM];  // attention output (bf16)

// ================= PTX helpers (base sm_103 features only) =================
__device__ __forceinline__ uint32_t smem_u32(const void* p) {
    uint32_t a;
    asm("{ .reg .u64 t; cvta.to.shared.u64 t, %1; cvt.u32.u64 %0, t; }" : "=r"(a) : "l"(p));
    return a;
}
__device__ __forceinline__ void cp16(uint32_t dst, const void* src) {
    asm volatile("cp.async.cg.shared.global [%0], [%1], 16;" :: "r"(dst), "l"(src));
}
__device__ __forceinline__ void cp_commit() {
    asm volatile("cp.async.commit_group;" ::: "memory");
}
template <int N>
__device__ __forceinline__ void cp_wait() {
    asm volatile("cp.async.wait_group %0;" :: "n"(N) : "memory");
}
#define LDSM_X4(r0, r1, r2, r3, addr) \
    asm volatile("ldmatrix.sync.aligned.m8n8.x4.shared.b16 {%0,%1,%2,%3}, [%4];" \
        : "=r"(r0), "=r"(r1), "=r"(r2), "=r"(r3) : "r"(addr))
#define LDSM_X4_T(r0, r1, r2, r3, addr) \
    asm volatile("ldmatrix.sync.aligned.m8n8.x4.trans.shared.b16 {%0,%1,%2,%3}, [%4];" \
        : "=r"(r0), "=r"(r1), "=r"(r2), "=r"(r3) : "r"(addr))
#define MMA16816(d, a0, a1, a2, a3, b0, b1) \
    asm volatile("mma.sync.aligned.m16n8k16.row.col.f32.bf16.bf16.f32 " \
        "{%0,%1,%2,%3}, {%4,%5,%6,%7}, {%8,%9}, {%0,%1,%2,%3};" \
        : "+f"((d)[0]), "+f"((d)[1]), "+f"((d)[2]), "+f"((d)[3]) \
        : "r"(a0), "r"(a1), "r"(a2), "r"(a3), "r"(b0), "r"(b1))

__device__ __forceinline__ uint32_t pack_bf16(float x, float y) {
    __nv_bfloat162 p = __floats2bfloat162_rn(x, y);
    return *reinterpret_cast<uint32_t*>(&p);
}

// scale * log2(e), folded into Q at projection time
#define QSCALE 0.1803368801111204f

// ---------------- merged LayerNorm, warp-per-row (fp32 in, bf16 out) ----------------
// 8 rows per CTA (one warp each), shfl-only reductions, no smem/barriers.
__global__ __launch_bounds__(256)
void ln_kernel(const float* __restrict__ kv, const float* __restrict__ query,
               __nv_bfloat16* __restrict__ y,
               const float* __restrict__ g_kv, const float* __restrict__ b_kv,
               const float* __restrict__ g_q,  const float* __restrict__ b_q)
{
    int row = blockIdx.x * 8 + (threadIdx.x >> 5);
    int lane = threadIdx.x & 31;
    int b = row / NCTX;
    int r = row - b * NCTX;
    const float* xr;
    const float *gg_p, *bb_p;
    if (r < NKV) { xr = kv    + ((long)b * NKV + r)        * DIM; gg_p = g_kv; bb_p = b_kv; }
    else         { xr = query + ((long)b * NQ + (r - NKV)) * DIM; gg_p = g_q;  bb_p = b_q;  }
    __nv_bfloat16* yr = y + (long)row * DIM;

    float4 v[8];
    float s = 0.f;
    #pragma unroll
    for (int c = 0; c < 8; c++) {
        v[c] = *(const float4*)(xr + (c * 32 + lane) * 4);
        s += v[c].x + v[c].y + v[c].z + v[c].w;
    }
    #pragma unroll
    for (int o = 16; o > 0; o >>= 1) s += __shfl_xor_sync(0xffffffffu, s, o);
    float mu = s * (1.f / DIM);

    float q = 0.f;
    #pragma unroll
    for (int c = 0; c < 8; c++) {
        float d0 = v[c].x - mu, d1 = v[c].y - mu, d2 = v[c].z - mu, d3 = v[c].w - mu;
        q += d0*d0 + d1*d1 + d2*d2 + d3*d3;
    }
    #pragma unroll
    for (int o = 16; o > 0; o >>= 1) q += __shfl_xor_sync(0xffffffffu, q, o);
    float rstd = rsqrtf(q * (1.f / DIM) + 1e-5f);

    #pragma unroll
    for (int c = 0; c < 8; c++) {
        int col = (c * 32 + lane) * 4;
        float4 gg = *(const float4*)(gg_p + col);
        float4 b4 = *(const float4*)(bb_p + col);
        float o0 = (v[c].x - mu) * rstd * gg.x + b4.x;
        float o1 = (v[c].y - mu) * rstd * gg.y + b4.y;
        float o2 = (v[c].z - mu) * rstd * gg.z + b4.z;
        float o3 = (v[c].w - mu) * rstd * gg.w + b4.w;
        uint2 u;
        u.x = pack_bf16(o0, o1);
        u.y = pack_bf16(o2, o3);
        *reinterpret_cast<uint2*>(yr + col) = u;
    }
}

// ---------------- weight transpose+convert (all 4 in one launch) ----------------
__global__ __launch_bounds__(256)
void wtrans_kernel(const float* __restrict__ W0, const float* __restrict__ W1,
                   const float* __restrict__ W2, const float* __restrict__ W3,
                   __nv_bfloat16* __restrict__ Wt)
{
    __shared__ float s[32][33];
    const float* W = (blockIdx.z == 0) ? W0 : (blockIdx.z == 1) ? W1
                   : (blockIdx.z == 2) ? W2 : W3;
    __nv_bfloat16* Wo = Wt + (long)blockIdx.z * DIM * DIM;
    int tx = threadIdx.x, ty = threadIdx.y;
    int n0 = blockIdx.x * 32, k0 = blockIdx.y * 32;
    #pragma unroll
    for (int i = 0; i < 32; i += 8)
        s[ty + i][tx] = W[(long)(k0 + ty + i) * DIM + n0 + tx];
    __syncthreads();
    #pragma unroll
    for (int i = 0; i < 32; i += 8)
        Wo[(long)(n0 + ty + i) * DIM + k0 + tx] = __float2bfloat16(s[tx][ty + i]);
}

// ================= shared GEMM machinery (R10-proven) =================
// 128x128 CTA tile, 8 warps (2M x 4N, warp 64x32), BK=64, ST=3, 256 threads.
#define GK        1024
#define NIT       16               // K / 64
#define ST        3
#define STAGE_B   32768
#define GEMM_SMEM (ST * STAGE_B + 1024)

struct GemmCtx {
    uint32_t base;
    const __nv_bfloat16 *Ab, *Bb;
    int tid, lane, wm, wn;
};

__device__ __forceinline__ void gemm_load_stage(const GemmCtx& g, int it) {
    uint32_t sA = g.base + (it % ST) * STAGE_B;
    uint32_t sB = sA + 16384;
    int row = g.tid >> 1;
    int cb  = (g.tid & 1) * 4;
    const __nv_bfloat16* ga = g.Ab + (long)row * GK + it * 64 + cb * 8;
    const __nv_bfloat16* gb = g.Bb + (long)row * GK + it * 64 + cb * 8;
    uint32_t ro = row * 128;
    #pragma unroll
    for (int c = 0; c < 4; c++) {
        uint32_t sw = (((cb + c) ^ (row & 7)) << 4);
        cp16(sA + ro + sw, ga + c * 8);
        cp16(sB + ro + sw, gb + c * 8);
    }
    cp_commit();
}

__device__ __forceinline__ void gemm_mainloop(const GemmCtx& g, float acc[4][4][4]) {
    const int a_r8 = (g.lane & 7) + ((g.lane >> 3) & 1) * 8;
    const int a_cq = (g.lane >> 4);
    const int b_r8 = (g.lane & 7) + ((g.lane >> 4) & 1) * 8;
    const int b_cq = (g.lane >> 3) & 1;

    gemm_load_stage(g, 0);
    gemm_load_stage(g, 1);

    for (int it = 0; it < NIT; it++) {
        cp_wait<1>();
        __syncthreads();
        if (it + 2 < NIT) gemm_load_stage(g, it + 2);
        else cp_commit();

        uint32_t sA = g.base + (it % ST) * STAGE_B;
        uint32_t sB = sA + 16384;

        #pragma unroll
        for (int ks = 0; ks < 4; ks++) {
            uint32_t a[4][4];
            #pragma unroll
            for (int i = 0; i < 4; i++) {
                int r = g.wm * 64 + i * 16 + a_r8;
                int c = ks * 2 + a_cq;
                LDSM_X4(a[i][0], a[i][1], a[i][2], a[i][3],
                        sA + r * 128 + ((c ^ (r & 7)) << 4));
            }
            uint32_t b[2][4];
            #pragma unroll
            for (int jj = 0; jj < 2; jj++) {
                int r = g.wn * 32 + jj * 16 + b_r8;
                int c = ks * 2 + b_cq;
                LDSM_X4(b[jj][0], b[jj][1], b[jj][2], b[jj][3],
                        sB + r * 128 + ((c ^ (r & 7)) << 4));
            }
            #pragma unroll
            for (int i = 0; i < 4; i++)
                #pragma unroll
                for (int j = 0; j < 4; j++)
                    MMA16816(acc[i][j], a[i][0], a[i][1], a[i][2], a[i][3],
                             b[j >> 1][(j & 1) * 2], b[j >> 1][(j & 1) * 2 + 1]);
        }
    }
}

// ---------------- fused Q/K/V projection GEMM (256 threads, R10) ----------------
__global__ __launch_bounds__(256)
void gemm_qkv_kernel(const __nv_bfloat16* __restrict__ A,
                     const __nv_bfloat16* __restrict__ wt,
                     const float* __restrict__ bq, const float* __restrict__ bk,
                     const float* __restrict__ bv,
                     __nv_bfloat16* __restrict__ qb, __nv_bfloat16* __restrict__ kb,
                     __nv_bfloat16* __restrict__ vb)
{
    const int x = blockIdx.x, y = blockIdx.y;
    const float* bias;
    __nv_bfloat16* Out;
    const __nv_bfloat16* Bt;
    long orow;
    int col0;
    float osc = 1.f;
    if (x < 16) {
        Bt   = wt + 1L * DIM * DIM + (long)x * 128 * GK;  // [Wk;Wv] contiguous
        bias = (x < 8) ? bk : bv;
        Out  = (x < 8) ? kb : vb;
        col0 = (x & 7) * 128;
        orow = (long)y * 128;
    } else {
        int ym = y % 20;
        if (ym < 16) return;                    // not a q-row block
        Bt   = wt + (long)(x - 16) * 128 * GK;  // Wq
        bias = bq;
        Out  = qb;
        col0 = (x - 16) * 128;
        orow = (long)(y / 20) * NQ + (long)(ym - 16) * 128;
        osc  = QSCALE;
    }

    extern __shared__ char smraw[];
    GemmCtx g;
    g.base = (smem_u32(smraw) + 1023u) & ~1023u;
    g.tid  = threadIdx.x;
    g.lane = g.tid & 31;
    int wid = g.tid >> 5;
    g.wm = wid & 1;
    g.wn = wid >> 1;
    g.Ab = A + (long)y * 128 * GK;
    g.Bb = Bt;

    float acc[4][4][4];
    #pragma unroll
    for (int i = 0; i < 4; i++)
        #pragma unroll
        for (int j = 0; j < 4; j++)
            #pragma unroll
            for (int q = 0; q < 4; q++) acc[i][j][q] = 0.f;

    gemm_mainloop(g, acc);

    const long rowbase = (orow + g.wm * 64) * (long)DIM;
    const int  cw = col0 + g.wn * 32;
    #pragma unroll
    for (int i = 0; i < 4; i++) {
        int rr = i * 16 + (g.lane >> 2);
        #pragma unroll
        for (int j = 0; j < 4; j++) {
            int cc = cw + j * 8 + (g.lane & 3) * 2;
            float bx = bias[cc], by = bias[cc + 1];
            long off0 = rowbase + (long)rr * DIM + cc;
            long off1 = off0 + 8L * DIM;
            *(uint32_t*)(Out + off0) = pack_bf16((acc[i][j][0] + bx) * osc,
                                                 (acc[i][j][1] + by) * osc);
            *(uint32_t*)(Out + off1) = pack_bf16((acc[i][j][2] + bx) * osc,
                                                 (acc[i][j][3] + by) * osc);
        }
    }
}

// ---------------- O projection GEMM (f32 out + bias + resid, 256 threads) ----------------
__global__ __launch_bounds__(256)
void gemm_o_kernel(const __nv_bfloat16* __restrict__ A,
                   const __nv_bfloat16* __restrict__ Bt,
                   const float* __restrict__ bias,
                   const float* __restrict__ resid,
                   float* __restrict__ C)
{
    extern __shared__ char smraw[];
    GemmCtx g;
    g.base = (smem_u32(smraw) + 1023u) & ~1023u;
    g.tid  = threadIdx.x;
    g.lane = g.tid & 31;
    int wid = g.tid >> 5;
    g.wm = wid & 1;
    g.wn = wid >> 1;
    g.Ab = A + (long)blockIdx.y * 128 * GK;
    g.Bb = Bt + (long)blockIdx.x * 128 * GK;

    float acc[4][4][4];
    #pragma unroll
    for (int i = 0; i < 4; i++)
        #pragma unroll
        for (int j = 0; j < 4; j++)
            #pragma unroll
            for (int q = 0; q < 4; q++) acc[i][j][q] = 0.f;

    gemm_mainloop(g, acc);

    const long rowbase = ((long)blockIdx.y * 128 + g.wm * 64) * (long)DIM;
    const int  col0    = blockIdx.x * 128 + g.wn * 32;
    #pragma unroll
    for (int i = 0; i < 4; i++) {
        int rr = i * 16 + (g.lane >> 2);
        #pragma unroll
        for (int j = 0; j < 4; j++) {
            int cc = col0 + j * 8 + (g.lane & 3) * 2;
            float bx = bias[cc], by = bias[cc + 1];
            long off0 = rowbase + (long)rr * DIM + cc;
            long off1 = off0 + 8L * DIM;
            float2 r0 = *(const float2*)(resid + off0);
            float2 r1 = *(const float2*)(resid + off1);
            float2 o0, o1;
            o0.x = acc[i][j][0] + bx + r0.x; o0.y = acc[i][j][1] + by + r0.y;
            o1.x = acc[i][j][2] + bx + r1.x; o1.y = acc[i][j][3] + by + r1.y;
            *(float2*)(C + off0) = o0;
            *(float2*)(C + off1) = o1;
        }
    }
}

// ---------------- Tensor-core flash attention (R12, fixed-offset softmax) ----------
// 256 q-rows per CTA (8 warps x 32 rows, two 16-row halves), 64-key tiles,
// 4-stage cp.async ring, one barrier per tile, K/V fragments reused (4:1).
#define NT_KV      (NCTX / 64)            // 40
#define KVST       4
#define ATTN_SMEM  (32768 + KVST * 16384) // Q 32KB + 4 stages (K 8KB + V 8KB)

__global__ __launch_bounds__(256, 1)
void fattn_kernel(const __nv_bfloat16* __restrict__ Q,
                  const __nv_bfloat16* __restrict__ K,
                  const __nv_bfloat16* __restrict__ V,
                  __nv_bfloat16* __restrict__ O)
{
    extern __shared__ char smraw[];
    uint32_t base = (smem_u32(smraw) + 127u) & ~127u;
    uint32_t sQ  = base;
    uint32_t sKV = base + 32768;

    const int tid  = threadIdx.x;
    const int lane = tid & 31;
    const int wq   = tid >> 5;
    const int qt = blockIdx.x, h = blockIdx.y, b = blockIdx.z;

    const __nv_bfloat16* Qg = Q + ((long)(b * NQ + qt * 256)) * DIM + h * DH;
    const __nv_bfloat16* Kg = K + (long)b * NCTX * DIM + h * DH;
    const __nv_bfloat16* Vg = V + (long)b * NCTX * DIM + h * DH;

    {
        int lr = tid;
        const __nv_bfloat16* src = Qg + (long)lr * DIM;
        #pragma unroll
        for (int c = 0; c < 8; c++)
            cp16(sQ + lr * 128 + ((c ^ (lr & 7)) << 4), src + c * 8);
    }
    const int kvr = tid >> 2;
    const int kvc = (tid & 3) * 2;
    auto load_kv = [&](int t) {
        uint32_t sK = sKV + (t % KVST) * 16384;
        const __nv_bfloat16* ks = Kg + (long)(t * 64 + kvr) * DIM + kvc * 8;
        const __nv_bfloat16* vs = Vg + (long)(t * 64 + kvr) * DIM + kvc * 8;
        #pragma unroll
        for (int c = 0; c < 2; c++) {
            uint32_t sw = ((kvc + c) ^ (kvr & 7)) << 4;
            cp16(sK + kvr * 128 + sw, ks + c * 8);
            cp16(sK + 8192 + kvr * 128 + sw, vs + c * 8);
        }
    };
    load_kv(0);
    cp_commit();
    load_kv(1);
    cp_commit();
    load_kv(2);
    cp_commit();
    cp_wait<2>();
    __syncthreads();

    uint32_t aq0[4][4], aq1[4][4];
    {
        int rb = (lane & 7) + ((lane >> 3) & 1) * 8;
        int cc = lane >> 4;
        #pragma unroll
        for (int ks = 0; ks < 4; ks++) {
            int c = ks * 2 + cc;
            int r0 = wq * 32 + rb;
            int r1 = wq * 32 + 16 + rb;
            LDSM_X4(aq0[ks][0], aq0[ks][1], aq0[ks][2], aq0[ks][3],
                    sQ + r0 * 128 + ((c ^ (r0 & 7)) << 4));
            LDSM_X4(aq1[ks][0], aq1[ks][1], aq1[ks][2], aq1[ks][3],
                    sQ + r1 * 128 + ((c ^ (r1 & 7)) << 4));
        }
    }

    float l00 = 0.f, l01 = 0.f, l10 = 0.f, l11 = 0.f;
    float o0[8][4], o1[8][4];
    #pragma unroll
    for (int nt = 0; nt < 8; nt++)
        #pragma unroll
        for (int q = 0; q < 4; q++) { o0[nt][q] = 0.f; o1[nt][q] = 0.f; }

    const int r_ab = (lane & 7) + ((lane >> 3) & 1) * 8;
    const int r_b  = (lane & 7) + ((lane >> 4) & 1) * 8;
    const int cq_a = lane >> 4;
    const int cq_b = (lane >> 3) & 1;

    for (int t = 0; t < NT_KV; t++) {
        if (t + 3 < NT_KV) load_kv(t + 3);
        cp_commit();

        uint32_t sK = sKV + (t % KVST) * 16384;
        uint32_t sV = sK + 8192;

        float st0[8][4], st1[8][4];
        #pragma unroll
        for (int nt = 0; nt < 8; nt++)
            #pragma unroll
            for (int q = 0; q < 4; q++) { st0[nt][q] = 0.f; st1[nt][q] = 0.f; }

        #pragma unroll
        for (int ks = 0; ks < 4; ks++) {
            #pragma unroll
            for (int kg = 0; kg < 4; kg++) {
                int r = kg * 16 + r_b;
                int c = ks * 2 + cq_b;
                uint32_t b0, b1, b2, b3;
                LDSM_X4(b0, b1, b2, b3, sK + r * 128 + ((c ^ (r & 7)) << 4));
                MMA16816(st0[2 * kg],     aq0[ks][0], aq0[ks][1], aq0[ks][2], aq0[ks][3], b0, b1);
                MMA16816(st0[2 * kg + 1], aq0[ks][0], aq0[ks][1], aq0[ks][2], aq0[ks][3], b2, b3);
                MMA16816(st1[2 * kg],     aq1[ks][0], aq1[ks][1], aq1[ks][2], aq1[ks][3], b0, b1);
                MMA16816(st1[2 * kg + 1], aq1[ks][0], aq1[ks][1], aq1[ks][2], aq1[ks][3], b2, b3);
            }
        }

        uint32_t pa0[4][4], pa1[4][4];
        #pragma unroll
        for (int nt = 0; nt < 8; nt++) {
            float a0 = exp2f(st0[nt][0]);
            float a1 = exp2f(st0[nt][1]);
            float a2 = exp2f(st0[nt][2]);
            float a3 = exp2f(st0[nt][3]);
            l00 += a0 + a1;
            l01 += a2 + a3;
            pa0[nt >> 1][(nt & 1) * 2 + 0] = pack_bf16(a0, a1);
            pa0[nt >> 1][(nt & 1) * 2 + 1] = pack_bf16(a2, a3);
            float c0 = exp2f(st1[nt][0]);
            float c1 = exp2f(st1[nt][1]);
            float c2 = exp2f(st1[nt][2]);
            float c3 = exp2f(st1[nt][3]);
            l10 += c0 + c1;
            l11 += c2 + c3;
            pa1[nt >> 1][(nt & 1) * 2 + 0] = pack_bf16(c0, c1);
            pa1[nt >> 1][(nt & 1) * 2 + 1] = pack_bf16(c2, c3);
        }

        #pragma unroll
        for (int kt = 0; kt < 4; kt++) {
            #pragma unroll
            for (int np = 0; np < 4; np++) {
                int r = kt * 16 + r_ab;
                int c = np * 2 + cq_a;
                uint32_t b0, b1, b2, b3;
                LDSM_X4_T(b0, b1, b2, b3, sV + r * 128 + ((c ^ (r & 7)) << 4));
                MMA16816(o0[2 * np],     pa0[kt][0], pa0[kt][1], pa0[kt][2], pa0[kt][3], b0, b1);
                MMA16816(o0[2 * np + 1], pa0[kt][0], pa0[kt][1], pa0[kt][2], pa0[kt][3], b2, b3);
                MMA16816(o1[2 * np],     pa1[kt][0], pa1[kt][1], pa1[kt][2], pa1[kt][3], b0, b1);
                MMA16816(o1[2 * np + 1], pa1[kt][0], pa1[kt][1], pa1[kt][2], pa1[kt][3], b2, b3);
            }
        }

        cp_wait<2>();
        __syncthreads();
    }

    l00 += __shfl_xor_sync(0xffffffffu, l00, 1);
    l00 += __shfl_xor_sync(0xffffffffu, l00, 2);
    l01 += __shfl_xor_sync(0xffffffffu, l01, 1);
    l01 += __shfl_xor_sync(0xffffffffu, l01, 2);
    l10 += __shfl_xor_sync(0xffffffffu, l10, 1);
    l10 += __shfl_xor_sync(0xffffffffu, l10, 2);
    l11 += __shfl_xor_sync(0xffffffffu, l11, 1);
    l11 += __shfl_xor_sync(0xffffffffu, l11, 2);

    float i00 = 1.f / l00, i01 = 1.f / l01, i10 = 1.f / l10, i11 = 1.f / l11;
    int row = qt * 256 + wq * 32 + (lane >> 2);
    __nv_bfloat16* Og = O + ((long)(b * NQ + row)) * DIM + h * DH + (lane & 3) * 2;
    #pragma unroll
    for (int nt = 0; nt < 8; nt++) {
        *(uint32_t*)(Og + nt * 8)             = pack_bf16(o0[nt][0] * i00, o0[nt][1] * i00);
        *(uint32_t*)(Og + 8L * DIM + nt * 8)  = pack_bf16(o0[nt][2] * i01, o0[nt][3] * i01);
        *(uint32_t*)(Og + 16L * DIM + nt * 8) = pack_bf16(o1[nt][0] * i10, o1[nt][1] * i10);
        *(uint32_t*)(Og + 24L * DIM + nt * 8) = pack_bf16(o1[nt][2] * i11, o1[nt][3] * i11);
    }
}

// ---------------- launch ----------------
extern "C" void kernel_launch(void* const* d_in, const int* in_sizes, int n_in,
                              void* d_out, int out_size)
{
    const float* query   = (const float*)d_in[0];
    const float* kv      = (const float*)d_in[1];
    const float* ln_q_g  = (const float*)d_in[2];
    const float* ln_q_b  = (const float*)d_in[3];
    const float* ln_kv_g = (const float*)d_in[4];
    const float* ln_kv_b = (const float*)d_in[5];
    const float* Wq = (const float*)d_in[6];
    const float* bq = (const float*)d_in[7];
    const float* Wk = (const float*)d_in[8];
    const float* bk = (const float*)d_in[9];
    const float* Wv = (const float*)d_in[10];
    const float* bv = (const float*)d_in[11];
    const float* Wo = (const float*)d_in[12];
    const float* bo = (const float*)d_in[13];
    float* out = (float*)d_out;

    __nv_bfloat16 *kvn, *wt, *qb, *kb, *vb, *ab;
    cudaGetSymbolAddress((void**)&kvn, g_kvn);
    cudaGetSymbolAddress((void**)&wt,  g_wt);
    cudaGetSymbolAddress((void**)&qb,  g_q);
    cudaGetSymbolAddress((void**)&kb,  g_k);
    cudaGetSymbolAddress((void**)&vb,  g_v);
    cudaGetSymbolAddress((void**)&ab,  g_att);

    cudaFuncSetAttribute((const void*)gemm_qkv_kernel,
                         cudaFuncAttributeMaxDynamicSharedMemorySize, GEMM_SMEM);
    cudaFuncSetAttribute((const void*)gemm_o_kernel,
                         cudaFuncAttributeMaxDynamicSharedMemorySize, GEMM_SMEM);
    cudaFuncSetAttribute((const void*)fattn_kernel,
                         cudaFuncAttributeMaxDynamicSharedMemorySize, ATTN_SMEM);

    // transpose+convert weights to bf16 [N][K] (one launch for all four)
    {
        dim3 grid(DIM / 32, DIM / 32, 4), blk(32, 8);
        wtrans_kernel<<<grid, blk>>>(Wq, Wk, Wv, Wo, wt);
    }

    // merged LayerNorm -> bf16 kvn (warp-per-row, 8 rows/CTA)
    ln_kernel<<<BATCH * NCTX / 8, 256>>>(kv, query, kvn,
                                         ln_kv_g, ln_kv_b, ln_q_g, ln_q_b);

    // fused Q + K + V projections (24 x-blocks: 8 K, 8 V, 8 Q), 256 threads/CTA
    {
        dim3 grid(24, BATCH * NCTX / 128, 1);
        gemm_qkv_kernel<<<grid, 256, GEMM_SMEM>>>(kvn, wt, bq, bk, bv, qb, kb, vb);
    }

    // tensor-core flash attention (bf16 in/out), 256 q-rows per CTA
    {
        dim3 grid(NQ / 256, HEADS, BATCH);
        fattn_kernel<<<grid, 256, ATTN_SMEM>>>(qb, kb, vb, ab);
    }

    // out = attn @ Wo + bo + residual(query), 128x128 tiles
    {
        dim3 grid(DIM / 128, BATCH * NQ / 128, 1);
        gemm_o_kernel<<<grid, 256, GEMM_SMEM>>>(ab, wt + 3L * DIM * DIM, bo, query, out);
    }
}

// round 15
// speedup vs baseline: 1.2038x; 1.0084x over previous
#include <cuda_runtime.h>
#include <cuda_bf16.h>
#include <cstdint>

#define DIM   1024
#define NQ    512
#define NKV   2048
#define NCTX  2560
#define BATCH 4
#define HEADS 16
#define DH    64

// ---------------- scratch (no allocs allowed) ----------------
__device__ __nv_bfloat16 g_kvn[(long)BATCH * NCTX * DIM];  // LN outputs (bf16)
__device__ __nv_bfloat16 g_wt [4L * DIM * DIM];            // transposed bf16 weights [n][k]
__device__ __nv_bfloat16 g_q  [(long)BATCH * NQ   * DIM];
__device__ __nv_bfloat16 g_k  [(long)BATCH * NCTX * DIM];
__device__ __nv_bfloat16 g_v  [(long)BATCH * NCTX * DIM];
__device__ __nv_bfloat16 g_att[(long)BATCH * NQ   * DIM];  // attention output (bf16)

// ================= PTX helpers (base sm_103 features only) =================
__device__ __forceinline__ uint32_t smem_u32(const void* p) {
    uint32_t a;
    asm("{ .reg .u64 t; cvta.to.shared.u64 t, %1; cvt.u32.u64 %0, t; }" : "=r"(a) : "l"(p));
    return a;
}
__device__ __forceinline__ void cp16(uint32_t dst, const void* src) {
    asm volatile("cp.async.cg.shared.global [%0], [%1], 16;" :: "r"(dst), "l"(src));
}
__device__ __forceinline__ void cp_commit() {
    asm volatile("cp.async.commit_group;" ::: "memory");
}
template <int N>
__device__ __forceinline__ void cp_wait() {
    asm volatile("cp.async.wait_group %0;" :: "n"(N) : "memory");
}
#define LDSM_X4(r0, r1, r2, r3, addr) \
    asm volatile("ldmatrix.sync.aligned.m8n8.x4.shared.b16 {%0,%1,%2,%3}, [%4];" \
        : "=r"(r0), "=r"(r1), "=r"(r2), "=r"(r3) : "r"(addr))
#define LDSM_X4_T(r0, r1, r2, r3, addr) \
    asm volatile("ldmatrix.sync.aligned.m8n8.x4.trans.shared.b16 {%0,%1,%2,%3}, [%4];" \
        : "=r"(r0), "=r"(r1), "=r"(r2), "=r"(r3) : "r"(addr))
#define MMA16816(d, a0, a1, a2, a3, b0, b1) \
    asm volatile("mma.sync.aligned.m16n8k16.row.col.f32.bf16.bf16.f32 " \
        "{%0,%1,%2,%3}, {%4,%5,%6,%7}, {%8,%9}, {%0,%1,%2,%3};" \
        : "+f"((d)[0]), "+f"((d)[1]), "+f"((d)[2]), "+f"((d)[3]) \
        : "r"(a0), "r"(a1), "r"(a2), "r"(a3), "r"(b0), "r"(b1))

__device__ __forceinline__ uint32_t pack_bf16(float x, float y) {
    __nv_bfloat162 p = __floats2bfloat162_rn(x, y);
    return *reinterpret_cast<uint32_t*>(&p);
}

// scale * log2(e), folded into Q at projection time
#define QSCALE 0.1803368801111204f

// ---------------- merged LayerNorm, warp-per-row (fp32 in, bf16 out) ----------------
__global__ __launch_bounds__(256)
void ln_kernel(const float* __restrict__ kv, const float* __restrict__ query,
               __nv_bfloat16* __restrict__ y,
               const float* __restrict__ g_kv, const float* __restrict__ b_kv,
               const float* __restrict__ g_q,  const float* __restrict__ b_q)
{
    int row = blockIdx.x * 8 + (threadIdx.x >> 5);
    int lane = threadIdx.x & 31;
    int b = row / NCTX;
    int r = row - b * NCTX;
    const float* xr;
    const float *gg_p, *bb_p;
    if (r < NKV) { xr = kv    + ((long)b * NKV + r)        * DIM; gg_p = g_kv; bb_p = b_kv; }
    else         { xr = query + ((long)b * NQ + (r - NKV)) * DIM; gg_p = g_q;  bb_p = b_q;  }
    __nv_bfloat16* yr = y + (long)row * DIM;

    float4 v[8];
    float s = 0.f;
    #pragma unroll
    for (int c = 0; c < 8; c++) {
        v[c] = *(const float4*)(xr + (c * 32 + lane) * 4);
        s += v[c].x + v[c].y + v[c].z + v[c].w;
    }
    #pragma unroll
    for (int o = 16; o > 0; o >>= 1) s += __shfl_xor_sync(0xffffffffu, s, o);
    float mu = s * (1.f / DIM);

    float q = 0.f;
    #pragma unroll
    for (int c = 0; c < 8; c++) {
        float d0 = v[c].x - mu, d1 = v[c].y - mu, d2 = v[c].z - mu, d3 = v[c].w - mu;
        q += d0*d0 + d1*d1 + d2*d2 + d3*d3;
    }
    #pragma unroll
    for (int o = 16; o > 0; o >>= 1) q += __shfl_xor_sync(0xffffffffu, q, o);
    float rstd = rsqrtf(q * (1.f / DIM) + 1e-5f);

    #pragma unroll
    for (int c = 0; c < 8; c++) {
        int col = (c * 32 + lane) * 4;
        float4 gg = *(const float4*)(gg_p + col);
        float4 b4 = *(const float4*)(bb_p + col);
        float o0 = (v[c].x - mu) * rstd * gg.x + b4.x;
        float o1 = (v[c].y - mu) * rstd * gg.y + b4.y;
        float o2 = (v[c].z - mu) * rstd * gg.z + b4.z;
        float o3 = (v[c].w - mu) * rstd * gg.w + b4.w;
        uint2 u;
        u.x = pack_bf16(o0, o1);
        u.y = pack_bf16(o2, o3);
        *reinterpret_cast<uint2*>(yr + col) = u;
    }
}

// ---------------- weight transpose+convert (all 4 in one launch) ----------------
__global__ __launch_bounds__(256)
void wtrans_kernel(const float* __restrict__ W0, const float* __restrict__ W1,
                   const float* __restrict__ W2, const float* __restrict__ W3,
                   __nv_bfloat16* __restrict__ Wt)
{
    __shared__ float s[32][33];
    const float* W = (blockIdx.z == 0) ? W0 : (blockIdx.z == 1) ? W1
                   : (blockIdx.z == 2) ? W2 : W3;
    __nv_bfloat16* Wo = Wt + (long)blockIdx.z * DIM * DIM;
    int tx = threadIdx.x, ty = threadIdx.y;
    int n0 = blockIdx.x * 32, k0 = blockIdx.y * 32;
    #pragma unroll
    for (int i = 0; i < 32; i += 8)
        s[ty + i][tx] = W[(long)(k0 + ty + i) * DIM + n0 + tx];
    __syncthreads();
    #pragma unroll
    for (int i = 0; i < 32; i += 8)
        Wo[(long)(n0 + ty + i) * DIM + k0 + tx] = __float2bfloat16(s[tx][ty + i]);
}

// ================= shared GEMM machinery (R10-proven) =================
// 128x128 CTA tile, 8 warps (2M x 4N, warp 64x32), BK=64, ST=3, 256 threads.
#define GK        1024
#define NIT       16               // K / 64
#define ST        3
#define STAGE_B   32768
#define GEMM_SMEM (ST * STAGE_B + 1024)

struct GemmCtx {
    uint32_t base;
    const __nv_bfloat16 *Ab, *Bb;
    int tid, lane, wm, wn;
};

__device__ __forceinline__ void gemm_load_stage(const GemmCtx& g, int it) {
    uint32_t sA = g.base + (it % ST) * STAGE_B;
    uint32_t sB = sA + 16384;
    int row = g.tid >> 1;
    int cb  = (g.tid & 1) * 4;
    const __nv_bfloat16* ga = g.Ab + (long)row * GK + it * 64 + cb * 8;
    const __nv_bfloat16* gb = g.Bb + (long)row * GK + it * 64 + cb * 8;
    uint32_t ro = row * 128;
    #pragma unroll
    for (int c = 0; c < 4; c++) {
        uint32_t sw = (((cb + c) ^ (row & 7)) << 4);
        cp16(sA + ro + sw, ga + c * 8);
        cp16(sB + ro + sw, gb + c * 8);
    }
    cp_commit();
}

__device__ __forceinline__ void gemm_mainloop(const GemmCtx& g, float acc[4][4][4]) {
    const int a_r8 = (g.lane & 7) + ((g.lane >> 3) & 1) * 8;
    const int a_cq = (g.lane >> 4);
    const int b_r8 = (g.lane & 7) + ((g.lane >> 4) & 1) * 8;
    const int b_cq = (g.lane >> 3) & 1;

    gemm_load_stage(g, 0);
    gemm_load_stage(g, 1);

    for (int it = 0; it < NIT; it++) {
        cp_wait<1>();
        __syncthreads();
        if (it + 2 < NIT) gemm_load_stage(g, it + 2);
        else cp_commit();

        uint32_t sA = g.base + (it % ST) * STAGE_B;
        uint32_t sB = sA + 16384;

        #pragma unroll
        for (int ks = 0; ks < 4; ks++) {
            uint32_t a[4][4];
            #pragma unroll
            for (int i = 0; i < 4; i++) {
                int r = g.wm * 64 + i * 16 + a_r8;
                int c = ks * 2 + a_cq;
                LDSM_X4(a[i][0], a[i][1], a[i][2], a[i][3],
                        sA + r * 128 + ((c ^ (r & 7)) << 4));
            }
            uint32_t b[2][4];
            #pragma unroll
            for (int jj = 0; jj < 2; jj++) {
                int r = g.wn * 32 + jj * 16 + b_r8;
                int c = ks * 2 + b_cq;
                LDSM_X4(b[jj][0], b[jj][1], b[jj][2], b[jj][3],
                        sB + r * 128 + ((c ^ (r & 7)) << 4));
            }
            #pragma unroll
            for (int i = 0; i < 4; i++)
                #pragma unroll
                for (int j = 0; j < 4; j++)
                    MMA16816(acc[i][j], a[i][0], a[i][1], a[i][2], a[i][3],
                             b[j >> 1][(j & 1) * 2], b[j >> 1][(j & 1) * 2 + 1]);
        }
    }
}

// ---------------- fused Q/K/V projection GEMM (256 threads, R10) ----------------
__global__ __launch_bounds__(256)
void gemm_qkv_kernel(const __nv_bfloat16* __restrict__ A,
                     const __nv_bfloat16* __restrict__ wt,
                     const float* __restrict__ bq, const float* __restrict__ bk,
                     const float* __restrict__ bv,
                     __nv_bfloat16* __restrict__ qb, __nv_bfloat16* __restrict__ kb,
                     __nv_bfloat16* __restrict__ vb)
{
    const int x = blockIdx.x, y = blockIdx.y;
    const float* bias;
    __nv_bfloat16* Out;
    const __nv_bfloat16* Bt;
    long orow;
    int col0;
    float osc = 1.f;
    if (x < 16) {
        Bt   = wt + 1L * DIM * DIM + (long)x * 128 * GK;  // [Wk;Wv] contiguous
        bias = (x < 8) ? bk : bv;
        Out  = (x < 8) ? kb : vb;
        col0 = (x & 7) * 128;
        orow = (long)y * 128;
    } else {
        int ym = y % 20;
        if (ym < 16) return;                    // not a q-row block
        Bt   = wt + (long)(x - 16) * 128 * GK;  // Wq
        bias = bq;
        Out  = qb;
        col0 = (x - 16) * 128;
        orow = (long)(y / 20) * NQ + (long)(ym - 16) * 128;
        osc  = QSCALE;
    }

    extern __shared__ char smraw[];
    GemmCtx g;
    g.base = (smem_u32(smraw) + 1023u) & ~1023u;
    g.tid  = threadIdx.x;
    g.lane = g.tid & 31;
    int wid = g.tid >> 5;
    g.wm = wid & 1;
    g.wn = wid >> 1;
    g.Ab = A + (long)y * 128 * GK;
    g.Bb = Bt;

    float acc[4][4][4];
    #pragma unroll
    for (int i = 0; i < 4; i++)
        #pragma unroll
        for (int j = 0; j < 4; j++)
            #pragma unroll
            for (int q = 0; q < 4; q++) acc[i][j][q] = 0.f;

    gemm_mainloop(g, acc);

    const long rowbase = (orow + g.wm * 64) * (long)DIM;
    const int  cw = col0 + g.wn * 32;
    #pragma unroll
    for (int i = 0; i < 4; i++) {
        int rr = i * 16 + (g.lane >> 2);
        #pragma unroll
        for (int j = 0; j < 4; j++) {
            int cc = cw + j * 8 + (g.lane & 3) * 2;
            float bx = bias[cc], by = bias[cc + 1];
            long off0 = rowbase + (long)rr * DIM + cc;
            long off1 = off0 + 8L * DIM;
            *(uint32_t*)(Out + off0) = pack_bf16((acc[i][j][0] + bx) * osc,
                                                 (acc[i][j][1] + by) * osc);
            *(uint32_t*)(Out + off1) = pack_bf16((acc[i][j][2] + bx) * osc,
                                                 (acc[i][j][3] + by) * osc);
        }
    }
}

// ---------------- O projection GEMM (f32 out + bias + resid, 256 threads) ----------------
__global__ __launch_bounds__(256)
void gemm_o_kernel(const __nv_bfloat16* __restrict__ A,
                   const __nv_bfloat16* __restrict__ Bt,
                   const float* __restrict__ bias,
                   const float* __restrict__ resid,
                   float* __restrict__ C)
{
    extern __shared__ char smraw[];
    GemmCtx g;
    g.base = (smem_u32(smraw) + 1023u) & ~1023u;
    g.tid  = threadIdx.x;
    g.lane = g.tid & 31;
    int wid = g.tid >> 5;
    g.wm = wid & 1;
    g.wn = wid >> 1;
    g.Ab = A + (long)blockIdx.y * 128 * GK;
    g.Bb = Bt + (long)blockIdx.x * 128 * GK;

    float acc[4][4][4];
    #pragma unroll
    for (int i = 0; i < 4; i++)
        #pragma unroll
        for (int j = 0; j < 4; j++)
            #pragma unroll
            for (int q = 0; q < 4; q++) acc[i][j][q] = 0.f;

    gemm_mainloop(g, acc);

    const long rowbase = ((long)blockIdx.y * 128 + g.wm * 64) * (long)DIM;
    const int  col0    = blockIdx.x * 128 + g.wn * 32;
    #pragma unroll
    for (int i = 0; i < 4; i++) {
        int rr = i * 16 + (g.lane >> 2);
        #pragma unroll
        for (int j = 0; j < 4; j++) {
            int cc = col0 + j * 8 + (g.lane & 3) * 2;
            float bx = bias[cc], by = bias[cc + 1];
            long off0 = rowbase + (long)rr * DIM + cc;
            long off1 = off0 + 8L * DIM;
            float2 r0 = *(const float2*)(resid + off0);
            float2 r1 = *(const float2*)(resid + off1);
            float2 o0, o1;
            o0.x = acc[i][j][0] + bx + r0.x; o0.y = acc[i][j][1] + by + r0.y;
            o1.x = acc[i][j][2] + bx + r1.x; o1.y = acc[i][j][3] + by + r1.y;
            *(float2*)(C + off0) = o0;
            *(float2*)(C + off1) = o1;
        }
    }
}

// ---------------- Tensor-core flash attention (kg-fused chains) ----------
// 256 q-rows per CTA (8 warps x 32 rows, two 16-row halves), 64-key tiles,
// 4-stage cp.async ring. Per key-group kg: S-MMA -> exp -> PV, so the four
// kg chains overlap MUFU with tensor. K/V fragments loaded once per warp.
#define NT_KV      (NCTX / 64)            // 40
#define KVST       4
#define ATTN_SMEM  (32768 + KVST * 16384) // Q 32KB + 4 stages (K 8KB + V 8KB)

__global__ __launch_bounds__(256, 1)
void fattn_kernel(const __nv_bfloat16* __restrict__ Q,
                  const __nv_bfloat16* __restrict__ K,
                  const __nv_bfloat16* __restrict__ V,
                  __nv_bfloat16* __restrict__ O)
{
    extern __shared__ char smraw[];
    uint32_t base = (smem_u32(smraw) + 127u) & ~127u;
    uint32_t sQ  = base;
    uint32_t sKV = base + 32768;

    const int tid  = threadIdx.x;
    const int lane = tid & 31;
    const int wq   = tid >> 5;
    const int qt = blockIdx.x, h = blockIdx.y, b = blockIdx.z;

    const __nv_bfloat16* Qg = Q + ((long)(b * NQ + qt * 256)) * DIM + h * DH;
    const __nv_bfloat16* Kg = K + (long)b * NCTX * DIM + h * DH;
    const __nv_bfloat16* Vg = V + (long)b * NCTX * DIM + h * DH;

    {
        int lr = tid;
        const __nv_bfloat16* src = Qg + (long)lr * DIM;
        #pragma unroll
        for (int c = 0; c < 8; c++)
            cp16(sQ + lr * 128 + ((c ^ (lr & 7)) << 4), src + c * 8);
    }
    const int kvr = tid >> 2;
    const int kvc = (tid & 3) * 2;
    auto load_kv = [&](int t) {
        uint32_t sK = sKV + (t % KVST) * 16384;
        const __nv_bfloat16* ks = Kg + (long)(t * 64 + kvr) * DIM + kvc * 8;
        const __nv_bfloat16* vs = Vg + (long)(t * 64 + kvr) * DIM + kvc * 8;
        #pragma unroll
        for (int c = 0; c < 2; c++) {
            uint32_t sw = ((kvc + c) ^ (kvr & 7)) << 4;
            cp16(sK + kvr * 128 + sw, ks + c * 8);
            cp16(sK + 8192 + kvr * 128 + sw, vs + c * 8);
        }
    };
    load_kv(0);
    cp_commit();
    load_kv(1);
    cp_commit();
    load_kv(2);
    cp_commit();
    cp_wait<2>();
    __syncthreads();

    uint32_t aq0[4][4], aq1[4][4];
    {
        int rb = (lane & 7) + ((lane >> 3) & 1) * 8;
        int cc = lane >> 4;
        #pragma unroll
        for (int ks = 0; ks < 4; ks++) {
            int c = ks * 2 + cc;
            int r0 = wq * 32 + rb;
            int r1 = wq * 32 + 16 + rb;
            LDSM_X4(aq0[ks][0], aq0[ks][1], aq0[ks][2], aq0[ks][3],
                    sQ + r0 * 128 + ((c ^ (r0 & 7)) << 4));
            LDSM_X4(aq1[ks][0], aq1[ks][1], aq1[ks][2], aq1[ks][3],
                    sQ + r1 * 128 + ((c ^ (r1 & 7)) << 4));
        }
    }

    float l00 = 0.f, l01 = 0.f, l10 = 0.f, l11 = 0.f;
    float o0[8][4], o1[8][4];
    #pragma unroll
    for (int nt = 0; nt < 8; nt++)
        #pragma unroll
        for (int q = 0; q < 4; q++) { o0[nt][q] = 0.f; o1[nt][q] = 0.f; }

    const int r_ab = (lane & 7) + ((lane >> 3) & 1) * 8;
    const int r_b  = (lane & 7) + ((lane >> 4) & 1) * 8;
    const int cq_a = lane >> 4;
    const int cq_b = (lane >> 3) & 1;

    for (int t = 0; t < NT_KV; t++) {
        if (t + 3 < NT_KV) load_kv(t + 3);
        cp_commit();

        uint32_t sK = sKV + (t % KVST) * 16384;
        uint32_t sV = sK + 8192;

        // per key-group: S-MMA (ks inner) -> exp/pack -> PV. Four independent
        // chains per tile; MUFU of kg overlaps tensor of kg+1.
        #pragma unroll
        for (int kg = 0; kg < 4; kg++) {
            // ---- S for keys [16kg,16kg+16): both halves ----
            float s0[2][4], s1[2][4];
            #pragma unroll
            for (int n = 0; n < 2; n++)
                #pragma unroll
                for (int q = 0; q < 4; q++) { s0[n][q] = 0.f; s1[n][q] = 0.f; }

            #pragma unroll
            for (int ks = 0; ks < 4; ks++) {
                int r = kg * 16 + r_b;
                int c = ks * 2 + cq_b;
                uint32_t b0, b1, b2, b3;
                LDSM_X4(b0, b1, b2, b3, sK + r * 128 + ((c ^ (r & 7)) << 4));
                MMA16816(s0[0], aq0[ks][0], aq0[ks][1], aq0[ks][2], aq0[ks][3], b0, b1);
                MMA16816(s0[1], aq0[ks][0], aq0[ks][1], aq0[ks][2], aq0[ks][3], b2, b3);
                MMA16816(s1[0], aq1[ks][0], aq1[ks][1], aq1[ks][2], aq1[ks][3], b0, b1);
                MMA16816(s1[1], aq1[ks][0], aq1[ks][1], aq1[ks][2], aq1[ks][3], b2, b3);
            }

            // ---- exp2 + pack + row-sum for this kg ----
            uint32_t p0[4], p1[4];
            #pragma unroll
            for (int n = 0; n < 2; n++) {
                float a0 = exp2f(s0[n][0]);
                float a1 = exp2f(s0[n][1]);
                float a2 = exp2f(s0[n][2]);
                float a3 = exp2f(s0[n][3]);
                l00 += a0 + a1;
                l01 += a2 + a3;
                p0[n * 2 + 0] = pack_bf16(a0, a1);
                p0[n * 2 + 1] = pack_bf16(a2, a3);
                float c0 = exp2f(s1[n][0]);
                float c1 = exp2f(s1[n][1]);
                float c2 = exp2f(s1[n][2]);
                float c3 = exp2f(s1[n][3]);
                l10 += c0 + c1;
                l11 += c2 + c3;
                p1[n * 2 + 0] = pack_bf16(c0, c1);
                p1[n * 2 + 1] = pack_bf16(c2, c3);
            }

            // ---- PV for key rows [16kg,16kg+16) ----
            #pragma unroll
            for (int np = 0; np < 4; np++) {
                int r = kg * 16 + r_ab;
                int c = np * 2 + cq_a;
                uint32_t b0, b1, b2, b3;
                LDSM_X4_T(b0, b1, b2, b3, sV + r * 128 + ((c ^ (r & 7)) << 4));
                MMA16816(o0[2 * np],     p0[0], p0[1], p0[2], p0[3], b0, b1);
                MMA16816(o0[2 * np + 1], p0[0], p0[1], p0[2], p0[3], b2, b3);
                MMA16816(o1[2 * np],     p1[0], p1[1], p1[2], p1[3], b0, b1);
                MMA16816(o1[2 * np + 1], p1[0], p1[1], p1[2], p1[3], b2, b3);
            }
        }

        cp_wait<2>();
        __syncthreads();
    }

    l00 += __shfl_xor_sync(0xffffffffu, l00, 1);
    l00 += __shfl_xor_sync(0xffffffffu, l00, 2);
    l01 += __shfl_xor_sync(0xffffffffu, l01, 1);
    l01 += __shfl_xor_sync(0xffffffffu, l01, 2);
    l10 += __shfl_xor_sync(0xffffffffu, l10, 1);
    l10 += __shfl_xor_sync(0xffffffffu, l10, 2);
    l11 += __shfl_xor_sync(0xffffffffu, l11, 1);
    l11 += __shfl_xor_sync(0xffffffffu, l11, 2);

    float i00 = 1.f / l00, i01 = 1.f / l01, i10 = 1.f / l10, i11 = 1.f / l11;
    int row = qt * 256 + wq * 32 + (lane >> 2);
    __nv_bfloat16* Og = O + ((long)(b * NQ + row)) * DIM + h * DH + (lane & 3) * 2;
    #pragma unroll
    for (int nt = 0; nt < 8; nt++) {
        *(uint32_t*)(Og + nt * 8)             = pack_bf16(o0[nt][0] * i00, o0[nt][1] * i00);
        *(uint32_t*)(Og + 8L * DIM + nt * 8)  = pack_bf16(o0[nt][2] * i01, o0[nt][3] * i01);
        *(uint32_t*)(Og + 16L * DIM + nt * 8) = pack_bf16(o1[nt][0] * i10, o1[nt][1] * i10);
        *(uint32_t*)(Og + 24L * DIM + nt * 8) = pack_bf16(o1[nt][2] * i11, o1[nt][3] * i11);
    }
}

// ---------------- launch ----------------
extern "C" void kernel_launch(void* const* d_in, const int* in_sizes, int n_in,
                              void* d_out, int out_size)
{
    const float* query   = (const float*)d_in[0];
    const float* kv      = (const float*)d_in[1];
    const float* ln_q_g  = (const float*)d_in[2];
    const float* ln_q_b  = (const float*)d_in[3];
    const float* ln_kv_g = (const float*)d_in[4];
    const float* ln_kv_b = (const float*)d_in[5];
    const float* Wq = (const float*)d_in[6];
    const float* bq = (const float*)d_in[7];
    const float* Wk = (const float*)d_in[8];
    const float* bk = (const float*)d_in[9];
    const float* Wv = (const float*)d_in[10];
    const float* bv = (const float*)d_in[11];
    const float* Wo = (const float*)d_in[12];
    const float* bo = (const float*)d_in[13];
    float* out = (float*)d_out;

    __nv_bfloat16 *kvn, *wt, *qb, *kb, *vb, *ab;
    cudaGetSymbolAddress((void**)&kvn, g_kvn);
    cudaGetSymbolAddress((void**)&wt,  g_wt);
    cudaGetSymbolAddress((void**)&qb,  g_q);
    cudaGetSymbolAddress((void**)&kb,  g_k);
    cudaGetSymbolAddress((void**)&vb,  g_v);
    cudaGetSymbolAddress((void**)&ab,  g_att);

    cudaFuncSetAttribute((const void*)gemm_qkv_kernel,
                         cudaFuncAttributeMaxDynamicSharedMemorySize, GEMM_SMEM);
    cudaFuncSetAttribute((const void*)gemm_o_kernel,
                         cudaFuncAttributeMaxDynamicSharedMemorySize, GEMM_SMEM);
    cudaFuncSetAttribute((const void*)fattn_kernel,
                         cudaFuncAttributeMaxDynamicSharedMemorySize, ATTN_SMEM);

    // transpose+convert weights to bf16 [N][K] (one launch for all four)
    {
        dim3 grid(DIM / 32, DIM / 32, 4), blk(32, 8);
        wtrans_kernel<<<grid, blk>>>(Wq, Wk, Wv, Wo, wt);
    }

    // merged LayerNorm -> bf16 kvn (warp-per-row, 8 rows/CTA)
    ln_kernel<<<BATCH * NCTX / 8, 256>>>(kv, query, kvn,
                                         ln_kv_g, ln_kv_b, ln_q_g, ln_q_b);

    // fused Q + K + V projections (24 x-blocks: 8 K, 8 V, 8 Q), 256 threads/CTA
    {
        dim3 grid(24, BATCH * NCTX / 128, 1);
        gemm_qkv_kernel<<<grid, 256, GEMM_SMEM>>>(kvn, wt, bq, bk, bv, qb, kb, vb);
    }

    // tensor-core flash attention (bf16 in/out), 256 q-rows per CTA
    {
        dim3 grid(NQ / 256, HEADS, BATCH);
        fattn_kernel<<<grid, 256, ATTN_SMEM>>>(qb, kb, vb, ab);
    }

    // out = attn @ Wo + bo + residual(query), 128x128 tiles
    {
        dim3 grid(DIM / 128, BATCH * NQ / 128, 1);
        gemm_o_kernel<<<grid, 256, GEMM_SMEM>>>(ab, wt + 3L * DIM * DIM, bo, query, out);
    }
}

// round 16
// speedup vs baseline: 1.2061x; 1.0019x over previous
#include <cuda_runtime.h>
#include <cuda_bf16.h>
#include <cstdint>

#define DIM   1024
#define NQ    512
#define NKV   2048
#define NCTX  2560
#define BATCH 4
#define HEADS 16
#define DH    64

// ---------------- scratch (no allocs allowed) ----------------
__device__ __nv_bfloat16 g_kvn[(long)BATCH * NCTX * DIM];  // LN outputs (bf16)
__device__ __nv_bfloat16 g_wt [4L * DIM * DIM];            // transposed bf16 weights [n][k]
__device__ __nv_bfloat16 g_q  [(long)BATCH * NQ   * DIM];
__device__ __nv_bfloat16 g_k  [(long)BATCH * NCTX * DIM];
__device__ __nv_bfloat16 g_v  [(long)BATCH * NCTX * DIM];
__device__ __nv_bfloat16 g_att[(long)BATCH * NQ   * DIM];  // attention output (bf16)

// ================= PTX helpers (base sm_103 features only) =================
__device__ __forceinline__ uint32_t smem_u32(const void* p) {
    uint32_t a;
    asm("{ .reg .u64 t; cvta.to.shared.u64 t, %1; cvt.u32.u64 %0, t; }" : "=r"(a) : "l"(p));
    return a;
}
__device__ __forceinline__ void cp16(uint32_t dst, const void* src) {
    asm volatile("cp.async.cg.shared.global [%0], [%1], 16;" :: "r"(dst), "l"(src));
}
__device__ __forceinline__ void cp_commit() {
    asm volatile("cp.async.commit_group;" ::: "memory");
}
template <int N>
__device__ __forceinline__ void cp_wait() {
    asm volatile("cp.async.wait_group %0;" :: "n"(N) : "memory");
}
#define LDSM_X4(r0, r1, r2, r3, addr) \
    asm volatile("ldmatrix.sync.aligned.m8n8.x4.shared.b16 {%0,%1,%2,%3}, [%4];" \
        : "=r"(r0), "=r"(r1), "=r"(r2), "=r"(r3) : "r"(addr))
#define LDSM_X4_T(r0, r1, r2, r3, addr) \
    asm volatile("ldmatrix.sync.aligned.m8n8.x4.trans.shared.b16 {%0,%1,%2,%3}, [%4];" \
        : "=r"(r0), "=r"(r1), "=r"(r2), "=r"(r3) : "r"(addr))
#define MMA16816(d, a0, a1, a2, a3, b0, b1) \
    asm volatile("mma.sync.aligned.m16n8k16.row.col.f32.bf16.bf16.f32 " \
        "{%0,%1,%2,%3}, {%4,%5,%6,%7}, {%8,%9}, {%0,%1,%2,%3};" \
        : "+f"((d)[0]), "+f"((d)[1]), "+f"((d)[2]), "+f"((d)[3]) \
        : "r"(a0), "r"(a1), "r"(a2), "r"(a3), "r"(b0), "r"(b1))

__device__ __forceinline__ uint32_t pack_bf16(float x, float y) {
    __nv_bfloat162 p = __floats2bfloat162_rn(x, y);
    return *reinterpret_cast<uint32_t*>(&p);
}

// single-instruction MUFU.EX2 (exp2f without fast-math is a multi-inst sequence)
__device__ __forceinline__ float ex2(float x) {
    float y;
    asm("ex2.approx.ftz.f32 %0, %1;" : "=f"(y) : "f"(x));
    return y;
}

// scale * log2(e), folded into Q at projection time
#define QSCALE 0.1803368801111204f

// ---------------- merged LayerNorm, warp-per-row (fp32 in, bf16 out) ----------------
__global__ __launch_bounds__(256)
void ln_kernel(const float* __restrict__ kv, const float* __restrict__ query,
               __nv_bfloat16* __restrict__ y,
               const float* __restrict__ g_kv, const float* __restrict__ b_kv,
               const float* __restrict__ g_q,  const float* __restrict__ b_q)
{
    int row = blockIdx.x * 8 + (threadIdx.x >> 5);
    int lane = threadIdx.x & 31;
    int b = row / NCTX;
    int r = row - b * NCTX;
    const float* xr;
    const float *gg_p, *bb_p;
    if (r < NKV) { xr = kv    + ((long)b * NKV + r)        * DIM; gg_p = g_kv; bb_p = b_kv; }
    else         { xr = query + ((long)b * NQ + (r - NKV)) * DIM; gg_p = g_q;  bb_p = b_q;  }
    __nv_bfloat16* yr = y + (long)row * DIM;

    float4 v[8];
    float s = 0.f;
    #pragma unroll
    for (int c = 0; c < 8; c++) {
        v[c] = *(const float4*)(xr + (c * 32 + lane) * 4);
        s += v[c].x + v[c].y + v[c].z + v[c].w;
    }
    #pragma unroll
    for (int o = 16; o > 0; o >>= 1) s += __shfl_xor_sync(0xffffffffu, s, o);
    float mu = s * (1.f / DIM);

    float q = 0.f;
    #pragma unroll
    for (int c = 0; c < 8; c++) {
        float d0 = v[c].x - mu, d1 = v[c].y - mu, d2 = v[c].z - mu, d3 = v[c].w - mu;
        q += d0*d0 + d1*d1 + d2*d2 + d3*d3;
    }
    #pragma unroll
    for (int o = 16; o > 0; o >>= 1) q += __shfl_xor_sync(0xffffffffu, q, o);
    float rstd = rsqrtf(q * (1.f / DIM) + 1e-5f);

    #pragma unroll
    for (int c = 0; c < 8; c++) {
        int col = (c * 32 + lane) * 4;
        float4 gg = *(const float4*)(gg_p + col);
        float4 b4 = *(const float4*)(bb_p + col);
        float o0 = (v[c].x - mu) * rstd * gg.x + b4.x;
        float o1 = (v[c].y - mu) * rstd * gg.y + b4.y;
        float o2 = (v[c].z - mu) * rstd * gg.z + b4.z;
        float o3 = (v[c].w - mu) * rstd * gg.w + b4.w;
        uint2 u;
        u.x = pack_bf16(o0, o1);
        u.y = pack_bf16(o2, o3);
        *reinterpret_cast<uint2*>(yr + col) = u;
    }
}

// ---------------- weight transpose+convert (all 4 in one launch) ----------------
__global__ __launch_bounds__(256)
void wtrans_kernel(const float* __restrict__ W0, const float* __restrict__ W1,
                   const float* __restrict__ W2, const float* __restrict__ W3,
                   __nv_bfloat16* __restrict__ Wt)
{
    __shared__ float s[32][33];
    const float* W = (blockIdx.z == 0) ? W0 : (blockIdx.z == 1) ? W1
                   : (blockIdx.z == 2) ? W2 : W3;
    __nv_bfloat16* Wo = Wt + (long)blockIdx.z * DIM * DIM;
    int tx = threadIdx.x, ty = threadIdx.y;
    int n0 = blockIdx.x * 32, k0 = blockIdx.y * 32;
    #pragma unroll
    for (int i = 0; i < 32; i += 8)
        s[ty + i][tx] = W[(long)(k0 + ty + i) * DIM + n0 + tx];
    __syncthreads();
    #pragma unroll
    for (int i = 0; i < 32; i += 8)
        Wo[(long)(n0 + ty + i) * DIM + k0 + tx] = __float2bfloat16(s[tx][ty + i]);
}

// ================= shared GEMM machinery (R10-proven) =================
// 128x128 CTA tile, 8 warps (2M x 4N, warp 64x32), BK=64, ST=3, 256 threads.
#define GK        1024
#define NIT       16               // K / 64
#define ST        3
#define STAGE_B   32768
#define GEMM_SMEM (ST * STAGE_B + 1024)

struct GemmCtx {
    uint32_t base;
    const __nv_bfloat16 *Ab, *Bb;
    int tid, lane, wm, wn;
};

__device__ __forceinline__ void gemm_load_stage(const GemmCtx& g, int it) {
    uint32_t sA = g.base + (it % ST) * STAGE_B;
    uint32_t sB = sA + 16384;
    int row = g.tid >> 1;
    int cb  = (g.tid & 1) * 4;
    const __nv_bfloat16* ga = g.Ab + (long)row * GK + it * 64 + cb * 8;
    const __nv_bfloat16* gb = g.Bb + (long)row * GK + it * 64 + cb * 8;
    uint32_t ro = row * 128;
    #pragma unroll
    for (int c = 0; c < 4; c++) {
        uint32_t sw = (((cb + c) ^ (row & 7)) << 4);
        cp16(sA + ro + sw, ga + c * 8);
        cp16(sB + ro + sw, gb + c * 8);
    }
    cp_commit();
}

__device__ __forceinline__ void gemm_mainloop(const GemmCtx& g, float acc[4][4][4]) {
    const int a_r8 = (g.lane & 7) + ((g.lane >> 3) & 1) * 8;
    const int a_cq = (g.lane >> 4);
    const int b_r8 = (g.lane & 7) + ((g.lane >> 4) & 1) * 8;
    const int b_cq = (g.lane >> 3) & 1;

    gemm_load_stage(g, 0);
    gemm_load_stage(g, 1);

    for (int it = 0; it < NIT; it++) {
        cp_wait<1>();
        __syncthreads();
        if (it + 2 < NIT) gemm_load_stage(g, it + 2);
        else cp_commit();

        uint32_t sA = g.base + (it % ST) * STAGE_B;
        uint32_t sB = sA + 16384;

        #pragma unroll
        for (int ks = 0; ks < 4; ks++) {
            uint32_t a[4][4];
            #pragma unroll
            for (int i = 0; i < 4; i++) {
                int r = g.wm * 64 + i * 16 + a_r8;
                int c = ks * 2 + a_cq;
                LDSM_X4(a[i][0], a[i][1], a[i][2], a[i][3],
                        sA + r * 128 + ((c ^ (r & 7)) << 4));
            }
            uint32_t b[2][4];
            #pragma unroll
            for (int jj = 0; jj < 2; jj++) {
                int r = g.wn * 32 + jj * 16 + b_r8;
                int c = ks * 2 + b_cq;
                LDSM_X4(b[jj][0], b[jj][1], b[jj][2], b[jj][3],
                        sB + r * 128 + ((c ^ (r & 7)) << 4));
            }
            #pragma unroll
            for (int i = 0; i < 4; i++)
                #pragma unroll
                for (int j = 0; j < 4; j++)
                    MMA16816(acc[i][j], a[i][0], a[i][1], a[i][2], a[i][3],
                             b[j >> 1][(j & 1) * 2], b[j >> 1][(j & 1) * 2 + 1]);
        }
    }
}

// ---------------- fused Q/K/V projection GEMM (256 threads, R10) ----------------
__global__ __launch_bounds__(256)
void gemm_qkv_kernel(const __nv_bfloat16* __restrict__ A,
                     const __nv_bfloat16* __restrict__ wt,
                     const float* __restrict__ bq, const float* __restrict__ bk,
                     const float* __restrict__ bv,
                     __nv_bfloat16* __restrict__ qb, __nv_bfloat16* __restrict__ kb,
                     __nv_bfloat16* __restrict__ vb)
{
    const int x = blockIdx.x, y = blockIdx.y;
    const float* bias;
    __nv_bfloat16* Out;
    const __nv_bfloat16* Bt;
    long orow;
    int col0;
    float osc = 1.f;
    if (x < 16) {
        Bt   = wt + 1L * DIM * DIM + (long)x * 128 * GK;  // [Wk;Wv] contiguous
        bias = (x < 8) ? bk : bv;
        Out  = (x < 8) ? kb : vb;
        col0 = (x & 7) * 128;
        orow = (long)y * 128;
    } else {
        int ym = y % 20;
        if (ym < 16) return;                    // not a q-row block
        Bt   = wt + (long)(x - 16) * 128 * GK;  // Wq
        bias = bq;
        Out  = qb;
        col0 = (x - 16) * 128;
        orow = (long)(y / 20) * NQ + (long)(ym - 16) * 128;
        osc  = QSCALE;
    }

    extern __shared__ char smraw[];
    GemmCtx g;
    g.base = (smem_u32(smraw) + 1023u) & ~1023u;
    g.tid  = threadIdx.x;
    g.lane = g.tid & 31;
    int wid = g.tid >> 5;
    g.wm = wid & 1;
    g.wn = wid >> 1;
    g.Ab = A + (long)y * 128 * GK;
    g.Bb = Bt;

    float acc[4][4][4];
    #pragma unroll
    for (int i = 0; i < 4; i++)
        #pragma unroll
        for (int j = 0; j < 4; j++)
            #pragma unroll
            for (int q = 0; q < 4; q++) acc[i][j][q] = 0.f;

    gemm_mainloop(g, acc);

    const long rowbase = (orow + g.wm * 64) * (long)DIM;
    const int  cw = col0 + g.wn * 32;
    #pragma unroll
    for (int i = 0; i < 4; i++) {
        int rr = i * 16 + (g.lane >> 2);
        #pragma unroll
        for (int j = 0; j < 4; j++) {
            int cc = cw + j * 8 + (g.lane & 3) * 2;
            float bx = bias[cc], by = bias[cc + 1];
            long off0 = rowbase + (long)rr * DIM + cc;
            long off1 = off0 + 8L * DIM;
            *(uint32_t*)(Out + off0) = pack_bf16((acc[i][j][0] + bx) * osc,
                                                 (acc[i][j][1] + by) * osc);
            *(uint32_t*)(Out + off1) = pack_bf16((acc[i][j][2] + bx) * osc,
                                                 (acc[i][j][3] + by) * osc);
        }
    }
}

// ---------------- O projection GEMM (f32 out + bias + resid, 256 threads) ----------------
__global__ __launch_bounds__(256)
void gemm_o_kernel(const __nv_bfloat16* __restrict__ A,
                   const __nv_bfloat16* __restrict__ Bt,
                   const float* __restrict__ bias,
                   const float* __restrict__ resid,
                   float* __restrict__ C)
{
    extern __shared__ char smraw[];
    GemmCtx g;
    g.base = (smem_u32(smraw) + 1023u) & ~1023u;
    g.tid  = threadIdx.x;
    g.lane = g.tid & 31;
    int wid = g.tid >> 5;
    g.wm = wid & 1;
    g.wn = wid >> 1;
    g.Ab = A + (long)blockIdx.y * 128 * GK;
    g.Bb = Bt + (long)blockIdx.x * 128 * GK;

    float acc[4][4][4];
    #pragma unroll
    for (int i = 0; i < 4; i++)
        #pragma unroll
        for (int j = 0; j < 4; j++)
            #pragma unroll
            for (int q = 0; q < 4; q++) acc[i][j][q] = 0.f;

    gemm_mainloop(g, acc);

    const long rowbase = ((long)blockIdx.y * 128 + g.wm * 64) * (long)DIM;
    const int  col0    = blockIdx.x * 128 + g.wn * 32;
    #pragma unroll
    for (int i = 0; i < 4; i++) {
        int rr = i * 16 + (g.lane >> 2);
        #pragma unroll
        for (int j = 0; j < 4; j++) {
            int cc = col0 + j * 8 + (g.lane & 3) * 2;
            float bx = bias[cc], by = bias[cc + 1];
            long off0 = rowbase + (long)rr * DIM + cc;
            long off1 = off0 + 8L * DIM;
            float2 r0 = *(const float2*)(resid + off0);
            float2 r1 = *(const float2*)(resid + off1);
            float2 o0, o1;
            o0.x = acc[i][j][0] + bx + r0.x; o0.y = acc[i][j][1] + by + r0.y;
            o1.x = acc[i][j][2] + bx + r1.x; o1.y = acc[i][j][3] + by + r1.y;
            *(float2*)(C + off0) = o0;
            *(float2*)(C + off1) = o1;
        }
    }
}

// ---------------- Tensor-core flash attention (kg-fused chains, MUFU ex2) ----------
// 256 q-rows per CTA (8 warps x 32 rows, two 16-row halves), 64-key tiles,
// 4-stage cp.async ring. Per key-group kg: S-MMA -> ex2 -> PV.
#define NT_KV      (NCTX / 64)            // 40
#define KVST       4
#define ATTN_SMEM  (32768 + KVST * 16384) // Q 32KB + 4 stages (K 8KB + V 8KB)

__global__ __launch_bounds__(256, 1)
void fattn_kernel(const __nv_bfloat16* __restrict__ Q,
                  const __nv_bfloat16* __restrict__ K,
                  const __nv_bfloat16* __restrict__ V,
                  __nv_bfloat16* __restrict__ O)
{
    extern __shared__ char smraw[];
    uint32_t base = (smem_u32(smraw) + 127u) & ~127u;
    uint32_t sQ  = base;
    uint32_t sKV = base + 32768;

    const int tid  = threadIdx.x;
    const int lane = tid & 31;
    const int wq   = tid >> 5;
    const int qt = blockIdx.x, h = blockIdx.y, b = blockIdx.z;

    const __nv_bfloat16* Qg = Q + ((long)(b * NQ + qt * 256)) * DIM + h * DH;
    const __nv_bfloat16* Kg = K + (long)b * NCTX * DIM + h * DH;
    const __nv_bfloat16* Vg = V + (long)b * NCTX * DIM + h * DH;

    {
        int lr = tid;
        const __nv_bfloat16* src = Qg + (long)lr * DIM;
        #pragma unroll
        for (int c = 0; c < 8; c++)
            cp16(sQ + lr * 128 + ((c ^ (lr & 7)) << 4), src + c * 8);
    }
    const int kvr = tid >> 2;
    const int kvc = (tid & 3) * 2;
    auto load_kv = [&](int t) {
        uint32_t sK = sKV + (t % KVST) * 16384;
        const __nv_bfloat16* ks = Kg + (long)(t * 64 + kvr) * DIM + kvc * 8;
        const __nv_bfloat16* vs = Vg + (long)(t * 64 + kvr) * DIM + kvc * 8;
        #pragma unroll
        for (int c = 0; c < 2; c++) {
            uint32_t sw = ((kvc + c) ^ (kvr & 7)) << 4;
            cp16(sK + kvr * 128 + sw, ks + c * 8);
            cp16(sK + 8192 + kvr * 128 + sw, vs + c * 8);
        }
    };
    load_kv(0);
    cp_commit();
    load_kv(1);
    cp_commit();
    load_kv(2);
    cp_commit();
    cp_wait<2>();
    __syncthreads();

    uint32_t aq0[4][4], aq1[4][4];
    {
        int rb = (lane & 7) + ((lane >> 3) & 1) * 8;
        int cc = lane >> 4;
        #pragma unroll
        for (int ks = 0; ks < 4; ks++) {
            int c = ks * 2 + cc;
            int r0 = wq * 32 + rb;
            int r1 = wq * 32 + 16 + rb;
            LDSM_X4(aq0[ks][0], aq0[ks][1], aq0[ks][2], aq0[ks][3],
                    sQ + r0 * 128 + ((c ^ (r0 & 7)) << 4));
            LDSM_X4(aq1[ks][0], aq1[ks][1], aq1[ks][2], aq1[ks][3],
                    sQ + r1 * 128 + ((c ^ (r1 & 7)) << 4));
        }
    }

    float l00 = 0.f, l01 = 0.f, l10 = 0.f, l11 = 0.f;
    float o0[8][4], o1[8][4];
    #pragma unroll
    for (int nt = 0; nt < 8; nt++)
        #pragma unroll
        for (int q = 0; q < 4; q++) { o0[nt][q] = 0.f; o1[nt][q] = 0.f; }

    const int r_ab = (lane & 7) + ((lane >> 3) & 1) * 8;
    const int r_b  = (lane & 7) + ((lane >> 4) & 1) * 8;
    const int cq_a = lane >> 4;
    const int cq_b = (lane >> 3) & 1;

    for (int t = 0; t < NT_KV; t++) {
        if (t + 3 < NT_KV) load_kv(t + 3);
        cp_commit();

        uint32_t sK = sKV + (t % KVST) * 16384;
        uint32_t sV = sK + 8192;

        #pragma unroll
        for (int kg = 0; kg < 4; kg++) {
            float s0[2][4], s1[2][4];
            #pragma unroll
            for (int n = 0; n < 2; n++)
                #pragma unroll
                for (int q = 0; q < 4; q++) { s0[n][q] = 0.f; s1[n][q] = 0.f; }

            #pragma unroll
            for (int ks = 0; ks < 4; ks++) {
                int r = kg * 16 + r_b;
                int c = ks * 2 + cq_b;
                uint32_t b0, b1, b2, b3;
                LDSM_X4(b0, b1, b2, b3, sK + r * 128 + ((c ^ (r & 7)) << 4));
                MMA16816(s0[0], aq0[ks][0], aq0[ks][1], aq0[ks][2], aq0[ks][3], b0, b1);
                MMA16816(s0[1], aq0[ks][0], aq0[ks][1], aq0[ks][2], aq0[ks][3], b2, b3);
                MMA16816(s1[0], aq1[ks][0], aq1[ks][1], aq1[ks][2], aq1[ks][3], b0, b1);
                MMA16816(s1[1], aq1[ks][0], aq1[ks][1], aq1[ks][2], aq1[ks][3], b2, b3);
            }

            uint32_t p0[4], p1[4];
            #pragma unroll
            for (int n = 0; n < 2; n++) {
                float a0 = ex2(s0[n][0]);
                float a1 = ex2(s0[n][1]);
                float a2 = ex2(s0[n][2]);
                float a3 = ex2(s0[n][3]);
                l00 += a0 + a1;
                l01 += a2 + a3;
                p0[n * 2 + 0] = pack_bf16(a0, a1);
                p0[n * 2 + 1] = pack_bf16(a2, a3);
                float c0 = ex2(s1[n][0]);
                float c1 = ex2(s1[n][1]);
                float c2 = ex2(s1[n][2]);
                float c3 = ex2(s1[n][3]);
                l10 += c0 + c1;
                l11 += c2 + c3;
                p1[n * 2 + 0] = pack_bf16(c0, c1);
                p1[n * 2 + 1] = pack_bf16(c2, c3);
            }

            #pragma unroll
            for (int np = 0; np < 4; np++) {
                int r = kg * 16 + r_ab;
                int c = np * 2 + cq_a;
                uint32_t b0, b1, b2, b3;
                LDSM_X4_T(b0, b1, b2, b3, sV + r * 128 + ((c ^ (r & 7)) << 4));
                MMA16816(o0[2 * np],     p0[0], p0[1], p0[2], p0[3], b0, b1);
                MMA16816(o0[2 * np + 1], p0[0], p0[1], p0[2], p0[3], b2, b3);
                MMA16816(o1[2 * np],     p1[0], p1[1], p1[2], p1[3], b0, b1);
                MMA16816(o1[2 * np + 1], p1[0], p1[1], p1[2], p1[3], b2, b3);
            }
        }

        cp_wait<2>();
        __syncthreads();
    }

    l00 += __shfl_xor_sync(0xffffffffu, l00, 1);
    l00 += __shfl_xor_sync(0xffffffffu, l00, 2);
    l01 += __shfl_xor_sync(0xffffffffu, l01, 1);
    l01 += __shfl_xor_sync(0xffffffffu, l01, 2);
    l10 += __shfl_xor_sync(0xffffffffu, l10, 1);
    l10 += __shfl_xor_sync(0xffffffffu, l10, 2);
    l11 += __shfl_xor_sync(0xffffffffu, l11, 1);
    l11 += __shfl_xor_sync(0xffffffffu, l11, 2);

    float i00 = 1.f / l00, i01 = 1.f / l01, i10 = 1.f / l10, i11 = 1.f / l11;
    int row = qt * 256 + wq * 32 + (lane >> 2);
    __nv_bfloat16* Og = O + ((long)(b * NQ + row)) * DIM + h * DH + (lane & 3) * 2;
    #pragma unroll
    for (int nt = 0; nt < 8; nt++) {
        *(uint32_t*)(Og + nt * 8)             = pack_bf16(o0[nt][0] * i00, o0[nt][1] * i00);
        *(uint32_t*)(Og + 8L * DIM + nt * 8)  = pack_bf16(o0[nt][2] * i01, o0[nt][3] * i01);
        *(uint32_t*)(Og + 16L * DIM + nt * 8) = pack_bf16(o1[nt][0] * i10, o1[nt][1] * i10);
        *(uint32_t*)(Og + 24L * DIM + nt * 8) = pack_bf16(o1[nt][2] * i11, o1[nt][3] * i11);
    }
}

// ---------------- launch ----------------
extern "C" void kernel_launch(void* const* d_in, const int* in_sizes, int n_in,
                              void* d_out, int out_size)
{
    const float* query   = (const float*)d_in[0];
    const float* kv      = (const float*)d_in[1];
    const float* ln_q_g  = (const float*)d_in[2];
    const float* ln_q_b  = (const float*)d_in[3];
    const float* ln_kv_g = (const float*)d_in[4];
    const float* ln_kv_b = (const float*)d_in[5];
    const float* Wq = (const float*)d_in[6];
    const float* bq = (const float*)d_in[7];
    const float* Wk = (const float*)d_in[8];
    const float* bk = (const float*)d_in[9];
    const float* Wv = (const float*)d_in[10];
    const float* bv = (const float*)d_in[11];
    const float* Wo = (const float*)d_in[12];
    const float* bo = (const float*)d_in[13];
    float* out = (float*)d_out;

    __nv_bfloat16 *kvn, *wt, *qb, *kb, *vb, *ab;
    cudaGetSymbolAddress((void**)&kvn, g_kvn);
    cudaGetSymbolAddress((void**)&wt,  g_wt);
    cudaGetSymbolAddress((void**)&qb,  g_q);
    cudaGetSymbolAddress((void**)&kb,  g_k);
    cudaGetSymbolAddress((void**)&vb,  g_v);
    cudaGetSymbolAddress((void**)&ab,  g_att);

    cudaFuncSetAttribute((const void*)gemm_qkv_kernel,
                         cudaFuncAttributeMaxDynamicSharedMemorySize, GEMM_SMEM);
    cudaFuncSetAttribute((const void*)gemm_o_kernel,
                         cudaFuncAttributeMaxDynamicSharedMemorySize, GEMM_SMEM);
    cudaFuncSetAttribute((const void*)fattn_kernel,
                         cudaFuncAttributeMaxDynamicSharedMemorySize, ATTN_SMEM);

    // transpose+convert weights to bf16 [N][K] (one launch for all four)
    {
        dim3 grid(DIM / 32, DIM / 32, 4), blk(32, 8);
        wtrans_kernel<<<grid, blk>>>(Wq, Wk, Wv, Wo, wt);
    }

    // merged LayerNorm -> bf16 kvn (warp-per-row, 8 rows/CTA)
    ln_kernel<<<BATCH * NCTX / 8, 256>>>(kv, query, kvn,
                                         ln_kv_g, ln_kv_b, ln_q_g, ln_q_b);

    // fused Q + K + V projections (24 x-blocks: 8 K, 8 V, 8 Q), 256 threads/CTA
    {
        dim3 grid(24, BATCH * NCTX / 128, 1);
        gemm_qkv_kernel<<<grid, 256, GEMM_SMEM>>>(kvn, wt, bq, bk, bv, qb, kb, vb);
    }

    // tensor-core flash attention (bf16 in/out), 256 q-rows per CTA
    {
        dim3 grid(NQ / 256, HEADS, BATCH);
        fattn_kernel<<<grid, 256, ATTN_SMEM>>>(qb, kb, vb, ab);
    }

    // out = attn @ Wo + bo + residual(query), 128x128 tiles
    {
        dim3 grid(DIM / 128, BATCH * NQ / 128, 1);
        gemm_o_kernel<<<grid, 256, GEMM_SMEM>>>(ab, wt + 3L * DIM * DIM, bo, query, out);
    }
}